// round 1
// baseline (speedup 1.0000x reference)
#include <cuda_runtime.h>
#include <math.h>

// Problem constants (fixed by the reference)
#define N_NODES 10000
#define N_EDGES 160000
#define IN_F    16
#define D       512
#define N_GRAPHS 64
#define N_OUT   18
#define BN_EPS  1e-5f

// ---------------------------------------------------------------------------
// Scratch (static __device__ arrays; no dynamic allocation allowed)
// ---------------------------------------------------------------------------
__device__ float g_h[N_NODES * D];        // current node features
__device__ float g_t[N_NODES * D];        // MLP hidden
__device__ float g_agg[N_NODES * D];      // aggregation buffer
__device__ float g_agg16[N_NODES * IN_F]; // layer-1 aggregation
__device__ float g_bnsum[D];
__device__ float g_bnsq[D];
__device__ float g_pool[N_GRAPHS * D];
__device__ float g_cnt[N_GRAPHS];

// ---------------------------------------------------------------------------
// Helpers: packed f32x2 FMA (Blackwell-only FFMA2 path) + vector atomics
// ---------------------------------------------------------------------------
typedef unsigned long long ull;

__device__ __forceinline__ void fma2(ull& d, ull a, ull b) {
    asm("fma.rn.f32x2 %0, %1, %2, %0;" : "+l"(d) : "l"(a), "l"(b));
}
__device__ __forceinline__ ull pack2(float x, float y) {
    ull r; asm("mov.b64 %0, {%1, %2};" : "=l"(r) : "f"(x), "f"(y)); return r;
}
__device__ __forceinline__ float2 unpack2(ull v) {
    float2 f; asm("mov.b64 {%0, %1}, %2;" : "=f"(f.x), "=f"(f.y) : "l"(v)); return f;
}
__device__ __forceinline__ void red_add_v4(float* p, float4 v) {
    asm volatile("red.global.add.v4.f32 [%0], {%1,%2,%3,%4};"
                 :: "l"(p), "f"(v.x), "f"(v.y), "f"(v.z), "f"(v.w) : "memory");
}

// ---------------------------------------------------------------------------
// Small utility kernels
// ---------------------------------------------------------------------------
__global__ void k_copy4(float* __restrict__ dst, const float* __restrict__ src, int n4) {
    int i = blockIdx.x * blockDim.x + threadIdx.x;
    if (i < n4) ((float4*)dst)[i] = ((const float4*)src)[i];
}

__global__ void k_zero_bn() {
    int i = blockIdx.x * blockDim.x + threadIdx.x;
    if (i < D) { g_bnsum[i] = 0.f; g_bnsq[i] = 0.f; }
}

__global__ void k_zero_pool() {
    int i = blockIdx.x * blockDim.x + threadIdx.x;
    if (i < N_GRAPHS * D) g_pool[i] = 0.f;
    if (i < N_GRAPHS) g_cnt[i] = 0.f;
}

// ---------------------------------------------------------------------------
// Layer-1 aggregation over IN_F=16 features
// ---------------------------------------------------------------------------
__global__ void k_scatter16(const float* __restrict__ x,
                            const int* __restrict__ src, const int* __restrict__ dst) {
    int idx = blockIdx.x * blockDim.x + threadIdx.x;
    if (idx >= N_EDGES * 4) return;
    int e = idx >> 2;
    int g = (idx & 3) << 2;
    int s = src[e], d = dst[e];
    float4 v = *(const float4*)&x[s * IN_F + g];
    red_add_v4(&g_agg16[d * IN_F + g], v);
}

// t = relu(agg16 @ W1a + b1a)   A:[N,16]  W:[16,512]
__global__ void k_gemm16(const float* __restrict__ W, const float* __restrict__ bias,
                         float* __restrict__ C) {
    int idx = blockIdx.x * blockDim.x + threadIdx.x;
    if (idx >= N_NODES * (D / 4)) return;
    int n = idx >> 7;
    int c = (idx & 127) << 2;
    float4 acc = *(const float4*)&bias[c];
    const float* arow = &g_agg16[n * IN_F];
#pragma unroll
    for (int k = 0; k < IN_F; k++) {
        float a = arow[k];
        float4 w = *(const float4*)&W[k * D + c];
        acc.x += a * w.x; acc.y += a * w.y; acc.z += a * w.z; acc.w += a * w.w;
    }
    acc.x = fmaxf(acc.x, 0.f); acc.y = fmaxf(acc.y, 0.f);
    acc.z = fmaxf(acc.z, 0.f); acc.w = fmaxf(acc.w, 0.f);
    *(float4*)&C[n * D + c] = acc;
}

// ---------------------------------------------------------------------------
// D=512 aggregation: agg[dst] += h[src]  (agg pre-initialized with h)
// ---------------------------------------------------------------------------
__global__ void k_scatter512(const float* __restrict__ hfeat, float* __restrict__ agg,
                             const int* __restrict__ src, const int* __restrict__ dst) {
    long long idx = (long long)blockIdx.x * blockDim.x + threadIdx.x;
    if (idx >= (long long)N_EDGES * (D / 4)) return;
    int e = (int)(idx >> 7);
    int g = ((int)idx & 127) << 2;
    int s = src[e], d = dst[e];
    float4 v = *(const float4*)&hfeat[s * D + g];
    red_add_v4(&agg[d * D + g], v);
}

// ---------------------------------------------------------------------------
// Main GEMM: C = relu(A[M x 512] @ W[512 x 512] + bias)
// BM=128, BN=128, BK=16, 256 threads, 8x8 per thread, f32x2 FMA inner loop
// ---------------------------------------------------------------------------
__global__ __launch_bounds__(256, 2)
void k_gemm512(const float* __restrict__ A, const float* __restrict__ W,
               const float* __restrict__ bias, float* __restrict__ C, int M) {
    __shared__ __align__(16) float As[16][128];   // [k][row] (transposed)
    __shared__ __align__(16) float Bs[16][128];   // [k][col]

    const int tid = threadIdx.x;
    const int tx = tid & 15;        // col group
    const int ty = tid >> 4;        // row group
    const int rowBase = blockIdx.x * 128;
    const int colBase = blockIdx.y * 128;

    ull acc[8][4];
#pragma unroll
    for (int i = 0; i < 8; i++)
#pragma unroll
        for (int j = 0; j < 4; j++) acc[i][j] = 0ull;

    for (int kt = 0; kt < 512; kt += 16) {
        // load A tile (128 rows x 16 cols) -> As transposed
#pragma unroll
        for (int l = 0; l < 2; l++) {
            int id = tid + l * 256;          // 0..511
            int r = id >> 2;                 // row in tile
            int c4 = id & 3;                 // which float4 of the 16 cols
            float4 v = make_float4(0.f, 0.f, 0.f, 0.f);
            int grow = rowBase + r;
            if (grow < M) v = *(const float4*)&A[grow * 512 + kt + c4 * 4];
            As[c4 * 4 + 0][r] = v.x;
            As[c4 * 4 + 1][r] = v.y;
            As[c4 * 4 + 2][r] = v.z;
            As[c4 * 4 + 3][r] = v.w;
        }
        // load B tile (16 rows x 128 cols)
#pragma unroll
        for (int l = 0; l < 2; l++) {
            int id = tid + l * 256;
            int r = id >> 5;                 // k row
            int c4 = id & 31;                // float4 within 128 cols
            float4 v = *(const float4*)&W[(kt + r) * 512 + colBase + c4 * 4];
            *(float4*)&Bs[r][c4 * 4] = v;
        }
        __syncthreads();

#pragma unroll
        for (int k = 0; k < 16; k++) {
            ull av[8];
#pragma unroll
            for (int i = 0; i < 8; i++) {
                float a = As[k][ty * 8 + i];
                av[i] = pack2(a, a);
            }
            const ull* brow = (const ull*)&Bs[k][tx * 8];
            ull b0 = brow[0], b1 = brow[1], b2 = brow[2], b3 = brow[3];
#pragma unroll
            for (int i = 0; i < 8; i++) {
                fma2(acc[i][0], av[i], b0);
                fma2(acc[i][1], av[i], b1);
                fma2(acc[i][2], av[i], b2);
                fma2(acc[i][3], av[i], b3);
            }
        }
        __syncthreads();
    }

    // epilogue: bias + relu
#pragma unroll
    for (int i = 0; i < 8; i++) {
        int row = rowBase + ty * 8 + i;
        if (row >= M) continue;
#pragma unroll
        for (int j = 0; j < 4; j++) {
            int col = colBase + tx * 8 + j * 2;
            float2 v = unpack2(acc[i][j]);
            v.x = fmaxf(v.x + bias[col], 0.f);
            v.y = fmaxf(v.y + bias[col + 1], 0.f);
            *(float2*)&C[row * 512 + col] = v;
        }
    }
}

// ---------------------------------------------------------------------------
// BatchNorm: stats then apply (training-mode batch stats, population var)
// ---------------------------------------------------------------------------
__global__ void k_bnstats(const float* __restrict__ h) {
    const int ROWS_PER = 200;       // 50 blocks * 200 = 10000
    int r0 = blockIdx.x * ROWS_PER;
    int c1 = threadIdx.x;           // 256 threads -> 2 channels each
    int c2 = threadIdx.x + 256;
    float s1 = 0.f, q1 = 0.f, s2 = 0.f, q2 = 0.f;
    int rend = min(r0 + ROWS_PER, N_NODES);
    for (int r = r0; r < rend; r++) {
        float a = h[r * D + c1];
        float b = h[r * D + c2];
        s1 += a; q1 += a * a;
        s2 += b; q2 += b * b;
    }
    atomicAdd(&g_bnsum[c1], s1); atomicAdd(&g_bnsq[c1], q1);
    atomicAdd(&g_bnsum[c2], s2); atomicAdd(&g_bnsq[c2], q2);
}

__global__ void k_bnapply(float* __restrict__ h,
                          const float* __restrict__ gamma, const float* __restrict__ beta) {
    int idx = blockIdx.x * blockDim.x + threadIdx.x;
    if (idx >= N_NODES * D) return;
    int c = idx & (D - 1);
    const float invN = 1.0f / N_NODES;
    float mean = g_bnsum[c] * invN;
    float var = g_bnsq[c] * invN - mean * mean;
    float sc = gamma[c] * rsqrtf(var + BN_EPS);
    h[idx] = (h[idx] - mean) * sc + beta[c];
}

// ---------------------------------------------------------------------------
// Global mean pool + head
// ---------------------------------------------------------------------------
__global__ void k_poolscatter(const float* __restrict__ h, const int* __restrict__ batch) {
    int idx = blockIdx.x * blockDim.x + threadIdx.x;
    if (idx >= N_NODES * (D / 4)) return;
    int n = idx >> 7;
    int g = (idx & 127) << 2;
    int b = batch[n];
    float4 v = *(const float4*)&h[n * D + g];
    red_add_v4(&g_pool[b * D + g], v);
}

__global__ void k_count(const int* __restrict__ batch) {
    int n = blockIdx.x * blockDim.x + threadIdx.x;
    if (n < N_NODES) atomicAdd(&g_cnt[batch[n]], 1.0f);
}

// 64 blocks x 512 threads: feats = tanh(pooled @ Wfc + bfc); logits = feats @ Wlog + blog
__global__ void k_head(const float* __restrict__ Wfc, const float* __restrict__ bfc,
                       const float* __restrict__ Wlog, const float* __restrict__ blog,
                       float* __restrict__ out) {
    __shared__ float sp[D];      // pooled (mean) features
    __shared__ float sf[D];      // tanh features
    int g = blockIdx.x;
    int t = threadIdx.x;
    float invc = 1.0f / fmaxf(g_cnt[g], 1.0f);
    sp[t] = g_pool[g * D + t] * invc;
    __syncthreads();

    float f = bfc[t];
    for (int k = 0; k < D; k++)
        f += sp[k] * Wfc[k * D + t];
    sf[t] = tanhf(f);
    __syncthreads();

    if (t < N_OUT) {
        float l = blog[t];
        for (int k = 0; k < D; k++)
            l += sf[k] * Wlog[k * N_OUT + t];
        out[g * N_OUT + t] = l;
    }
}

// ---------------------------------------------------------------------------
// Launcher
// ---------------------------------------------------------------------------
extern "C" void kernel_launch(void* const* d_in, const int* in_sizes, int n_in,
                              void* d_out, int out_size) {
    const float* x     = (const float*)d_in[0];
    const int*   ei    = (const int*)d_in[1];
    const int*   batch = (const int*)d_in[2];
    const float* W1a   = (const float*)d_in[3];
    const float* b1a   = (const float*)d_in[4];
    const float* W1b   = (const float*)d_in[5];
    const float* b1b   = (const float*)d_in[6];
    const float* Wa    = (const float*)d_in[7];
    const float* ba    = (const float*)d_in[8];
    const float* Wb    = (const float*)d_in[9];
    const float* bb    = (const float*)d_in[10];
    const float* bn_g  = (const float*)d_in[11];
    const float* bn_b  = (const float*)d_in[12];
    const float* Wfc   = (const float*)d_in[13];
    const float* bfc   = (const float*)d_in[14];
    const float* Wlog  = (const float*)d_in[15];
    const float* blog  = (const float*)d_in[16];
    float* out = (float*)d_out;

    const int* src = ei;
    const int* dst = ei + N_EDGES;

    float *h, *t, *agg, *agg16;
    cudaGetSymbolAddress((void**)&h,     g_h);
    cudaGetSymbolAddress((void**)&t,     g_t);
    cudaGetSymbolAddress((void**)&agg,   g_agg);
    cudaGetSymbolAddress((void**)&agg16, g_agg16);

    const int TB = 256;
    dim3 gemmGrid((N_NODES + 127) / 128, 4);

    // ---- layer 1 ----
    k_copy4<<<(N_NODES * IN_F / 4 + TB - 1) / TB, TB>>>(agg16, x, N_NODES * IN_F / 4);
    k_scatter16<<<(N_EDGES * 4 + TB - 1) / TB, TB>>>(x, src, dst);
    k_gemm16<<<(N_NODES * 128 + TB - 1) / TB, TB>>>(W1a, b1a, t);
    k_gemm512<<<gemmGrid, TB>>>(t, W1b, b1b, h, N_NODES);
    k_zero_bn<<<2, 256>>>();
    k_bnstats<<<50, 256>>>(h);
    k_bnapply<<<(N_NODES * D + TB - 1) / TB, TB>>>(h, bn_g, bn_b);

    // ---- layers 2..5 ----
    for (int i = 0; i < 4; i++) {
        k_copy4<<<(N_NODES * D / 4 + TB - 1) / TB, TB>>>(agg, h, N_NODES * D / 4);
        k_scatter512<<<(N_EDGES * 128 + TB - 1) / TB, TB>>>(h, agg, src, dst);
        k_gemm512<<<gemmGrid, TB>>>(agg, Wa + (size_t)i * D * D, ba + i * D, t, N_NODES);
        k_gemm512<<<gemmGrid, TB>>>(t,   Wb + (size_t)i * D * D, bb + i * D, h, N_NODES);
        k_zero_bn<<<2, 256>>>();
        k_bnstats<<<50, 256>>>(h);
        k_bnapply<<<(N_NODES * D + TB - 1) / TB, TB>>>(h, bn_g + (i + 1) * D, bn_b + (i + 1) * D);
    }

    // ---- pooling + head ----
    k_zero_pool<<<(N_GRAPHS * D + TB - 1) / TB, TB>>>();
    k_poolscatter<<<(N_NODES * 128 + TB - 1) / TB, TB>>>(h, batch);
    k_count<<<(N_NODES + TB - 1) / TB, TB>>>(batch);
    k_head<<<N_GRAPHS, D>>>(Wfc, bfc, Wlog, blog, out);
}

// round 4
// speedup vs baseline: 1.6342x; 1.6342x over previous
#include <cuda_runtime.h>
#include <cuda_bf16.h>
#include <stdint.h>
#include <math.h>

#define N_NODES 10000
#define N_EDGES 160000
#define IN_F    16
#define D       512
#define N_GRAPHS 64
#define N_OUT   18
#define BN_EPS  1e-5f

// ---------------------------------------------------------------------------
// Scratch
// ---------------------------------------------------------------------------
__device__ float g_h[N_NODES * D];
__device__ float g_t[N_NODES * D];
__device__ float g_agg[N_NODES * D];
__device__ float g_agg16[N_NODES * IN_F];
__device__ float g_bnsum[D];
__device__ float g_bnsq[D];
__device__ float g_pool[N_GRAPHS * D];
__device__ float g_cnt[N_GRAPHS];
// pre-converted, transposed weights: Bt[n][k] = W[k][n], split hi/lo bf16
__device__ __nv_bfloat16 g_Whi[9 * D * D];
__device__ __nv_bfloat16 g_Wlo[9 * D * D];

typedef unsigned long long ull;

__device__ __forceinline__ void red_add_v4(float* p, float4 v) {
    asm volatile("red.global.add.v4.f32 [%0], {%1,%2,%3,%4};"
                 :: "l"(p), "f"(v.x), "f"(v.y), "f"(v.z), "f"(v.w) : "memory");
}
__device__ __forceinline__ uint32_t smem_u32(const void* p) {
    uint32_t a;
    asm("{ .reg .u64 t; cvta.to.shared.u64 t, %1; cvt.u32.u64 %0, t; }" : "=r"(a) : "l"(p));
    return a;
}
__device__ __forceinline__ void ldsm4(uint32_t* r, uint32_t p) {
    asm volatile("ldmatrix.sync.aligned.m8n8.x4.shared.b16 {%0,%1,%2,%3}, [%4];"
                 : "=r"(r[0]), "=r"(r[1]), "=r"(r[2]), "=r"(r[3]) : "r"(p));
}
__device__ __forceinline__ void ldsm2(uint32_t* r, uint32_t p) {
    asm volatile("ldmatrix.sync.aligned.m8n8.x2.shared.b16 {%0,%1}, [%2];"
                 : "=r"(r[0]), "=r"(r[1]) : "r"(p));
}
__device__ __forceinline__ void mma16816(float* d, const uint32_t* a, const uint32_t* b) {
    asm volatile(
        "mma.sync.aligned.m16n8k16.row.col.f32.bf16.bf16.f32 "
        "{%0,%1,%2,%3}, {%4,%5,%6,%7}, {%8,%9}, {%0,%1,%2,%3};"
        : "+f"(d[0]), "+f"(d[1]), "+f"(d[2]), "+f"(d[3])
        : "r"(a[0]), "r"(a[1]), "r"(a[2]), "r"(a[3]), "r"(b[0]), "r"(b[1]));
}

// ---------------------------------------------------------------------------
// Utility kernels
// ---------------------------------------------------------------------------
__global__ void k_copy4(float* __restrict__ dst, const float* __restrict__ src, int n4) {
    int i = blockIdx.x * blockDim.x + threadIdx.x;
    if (i < n4) ((float4*)dst)[i] = ((const float4*)src)[i];
}
__global__ void k_zero_bn() {
    int i = blockIdx.x * blockDim.x + threadIdx.x;
    if (i < D) { g_bnsum[i] = 0.f; g_bnsq[i] = 0.f; }
}
__global__ void k_zero_pool() {
    int i = blockIdx.x * blockDim.x + threadIdx.x;
    if (i < N_GRAPHS * D) g_pool[i] = 0.f;
    if (i < N_GRAPHS) g_cnt[i] = 0.f;
}

// Weight convert + transpose: out[m][n][k] = split(W_m[k][n])
__global__ void k_convW(const float* __restrict__ W1b, const float* __restrict__ Wa,
                        const float* __restrict__ Wb) {
    __shared__ float tile[32][33];
    int m = blockIdx.z;
    const float* W = (m == 0) ? W1b
                   : ((m & 1) ? Wa + (size_t)((m - 1) >> 1) * D * D
                              : Wb + (size_t)((m - 2) >> 1) * D * D);
    int tx = threadIdx.x, ty = threadIdx.y;
    int n0 = blockIdx.x * 32, k0 = blockIdx.y * 32;
#pragma unroll
    for (int j = 0; j < 32; j += 8)
        tile[ty + j][tx] = W[(k0 + ty + j) * D + n0 + tx];
    __syncthreads();
#pragma unroll
    for (int j = 0; j < 32; j += 8) {
        float v = tile[tx][ty + j];
        int n = n0 + ty + j, k = k0 + tx;
        __nv_bfloat16 hi = __float2bfloat16(v);
        __nv_bfloat16 lo = __float2bfloat16(v - __bfloat162float(hi));
        size_t o = (size_t)m * D * D + (size_t)n * D + k;
        g_Whi[o] = hi;
        g_Wlo[o] = lo;
    }
}

// ---------------------------------------------------------------------------
// Layer-1 aggregation + small GEMM (IN_F=16)
// ---------------------------------------------------------------------------
__global__ void k_scatter16(const float* __restrict__ x,
                            const int* __restrict__ src, const int* __restrict__ dst) {
    int idx = blockIdx.x * blockDim.x + threadIdx.x;
    if (idx >= N_EDGES * 4) return;
    int e = idx >> 2;
    int g = (idx & 3) << 2;
    int s = src[e], d = dst[e];
    float4 v = *(const float4*)&x[s * IN_F + g];
    red_add_v4(&g_agg16[d * IN_F + g], v);
}

__global__ void k_gemm16(const float* __restrict__ W, const float* __restrict__ bias,
                         float* __restrict__ C) {
    int idx = blockIdx.x * blockDim.x + threadIdx.x;
    if (idx >= N_NODES * (D / 4)) return;
    int n = idx >> 7;
    int c = (idx & 127) << 2;
    float4 acc = *(const float4*)&bias[c];
    const float* arow = &g_agg16[n * IN_F];
#pragma unroll
    for (int k = 0; k < IN_F; k++) {
        float a = arow[k];
        float4 w = *(const float4*)&W[k * D + c];
        acc.x += a * w.x; acc.y += a * w.y; acc.z += a * w.z; acc.w += a * w.w;
    }
    acc.x = fmaxf(acc.x, 0.f); acc.y = fmaxf(acc.y, 0.f);
    acc.z = fmaxf(acc.z, 0.f); acc.w = fmaxf(acc.w, 0.f);
    *(float4*)&C[n * D + c] = acc;
}

// ---------------------------------------------------------------------------
// D=512 aggregation
// ---------------------------------------------------------------------------
__global__ void k_scatter512(const float* __restrict__ hfeat, float* __restrict__ agg,
                             const int* __restrict__ src, const int* __restrict__ dst) {
    long long idx = (long long)blockIdx.x * blockDim.x + threadIdx.x;
    if (idx >= (long long)N_EDGES * (D / 4)) return;
    int e = (int)(idx >> 7);
    int g = ((int)idx & 127) << 2;
    int s = src[e], d = dst[e];
    float4 v = *(const float4*)&hfeat[s * D + g];
    red_add_v4(&agg[d * D + g], v);
}

// ---------------------------------------------------------------------------
// HMMA GEMM: C[M x 512] = relu(A @ W + bias), W pre-transposed/split bf16.
// BM=128, BN=128, BK=64; 8 warps (4 M x 2 N), warp tile 32x64.
// 3-term split: Ahi*Bhi + Ahi*Blo + Alo*Bhi accumulated in fp32.
// ---------------------------------------------------------------------------
#define BM 128
#define BN 128
#define BK 64
#define SSTR 72                      // padded smem row stride in bf16 elems
#define TILE_ELEMS (128 * SSTR)      // 9216 bf16 per array
#define GEMM_SMEM (4 * TILE_ELEMS * 2)  // 73728 bytes

__global__ __launch_bounds__(256)
void k_gemm512_mma(const float* __restrict__ A,
                   const __nv_bfloat16* __restrict__ Bthi,
                   const __nv_bfloat16* __restrict__ Btlo,
                   const float* __restrict__ bias,
                   float* __restrict__ C, int M) {
    extern __shared__ __nv_bfloat16 sm[];
    __nv_bfloat16* sAhi = sm;
    __nv_bfloat16* sAlo = sm + TILE_ELEMS;
    __nv_bfloat16* sBhi = sm + 2 * TILE_ELEMS;
    __nv_bfloat16* sBlo = sm + 3 * TILE_ELEMS;

    const int tid = threadIdx.x;
    const int lane = tid & 31;
    const int warp = tid >> 5;
    const int wm = warp & 3;     // 4 warps over M
    const int wn = warp >> 2;    // 2 warps over N
    const int rowBase = blockIdx.x * BM;
    const int colBase = blockIdx.y * BN;

    const uint32_t aHiB = smem_u32(sAhi);
    const uint32_t aLoB = smem_u32(sAlo);
    const uint32_t bHiB = smem_u32(sBhi);
    const uint32_t bLoB = smem_u32(sBlo);

    float acc[2][8][4];
#pragma unroll
    for (int mi = 0; mi < 2; mi++)
#pragma unroll
        for (int ni = 0; ni < 8; ni++)
#pragma unroll
            for (int j = 0; j < 4; j++) acc[mi][ni][j] = 0.f;

    for (int kc = 0; kc < D / BK; kc++) {
        const int k0 = kc * BK;
        // ---- A tile: 128 rows x 64 f32 -> hi/lo bf16 (row-major, padded)
#pragma unroll
        for (int t = 0; t < 8; t++) {
            int lin = tid + t * 256;         // 0..2047
            int r = lin >> 4;                // 0..127
            int c4 = lin & 15;               // float4 within 64 cols
            float4 v = make_float4(0.f, 0.f, 0.f, 0.f);
            if (rowBase + r < M) v = *(const float4*)&A[(size_t)(rowBase + r) * D + k0 + c4 * 4];
            __nv_bfloat16 h0 = __float2bfloat16(v.x), h1 = __float2bfloat16(v.y);
            __nv_bfloat16 h2 = __float2bfloat16(v.z), h3 = __float2bfloat16(v.w);
            __nv_bfloat16 l0 = __float2bfloat16(v.x - __bfloat162float(h0));
            __nv_bfloat16 l1 = __float2bfloat16(v.y - __bfloat162float(h1));
            __nv_bfloat16 l2 = __float2bfloat16(v.z - __bfloat162float(h2));
            __nv_bfloat16 l3 = __float2bfloat16(v.w - __bfloat162float(h3));
            ull ph = (ull)__bfloat16_as_ushort(h0) | ((ull)__bfloat16_as_ushort(h1) << 16)
                   | ((ull)__bfloat16_as_ushort(h2) << 32) | ((ull)__bfloat16_as_ushort(h3) << 48);
            ull pl = (ull)__bfloat16_as_ushort(l0) | ((ull)__bfloat16_as_ushort(l1) << 16)
                   | ((ull)__bfloat16_as_ushort(l2) << 32) | ((ull)__bfloat16_as_ushort(l3) << 48);
            int off = r * SSTR + c4 * 4;
            *(ull*)&sAhi[off] = ph;
            *(ull*)&sAlo[off] = pl;
        }
        // ---- B tile: 128 n-rows x 64 k-cols bf16 (hi/lo), 16B copies
#pragma unroll
        for (int t = 0; t < 4; t++) {
            int lin = tid + t * 256;         // 0..1023
            int r = lin >> 3;                // 0..127
            int c8 = lin & 7;                // uint4 within 64 bf16
            size_t gi = (size_t)(colBase + r) * D + k0 + c8 * 8;
            int off = r * SSTR + c8 * 8;
            *(uint4*)&sBhi[off] = *(const uint4*)&Bthi[gi];
            *(uint4*)&sBlo[off] = *(const uint4*)&Btlo[gi];
        }
        __syncthreads();

        // ---- compute: 4 k-steps of 16
#pragma unroll
        for (int ks = 0; ks < 4; ks++) {
            const int kk = ks * 16;
            uint32_t ahi[2][4], alo[2][4];
#pragma unroll
            for (int mi = 0; mi < 2; mi++) {
                int row = wm * 32 + mi * 16 + (lane & 15);
                int col = kk + (lane >> 4) * 8;
                uint32_t off = (uint32_t)(row * SSTR + col) * 2;
                ldsm4(ahi[mi], aHiB + off);
                ldsm4(alo[mi], aLoB + off);
            }
#pragma unroll
            for (int ni = 0; ni < 8; ni++) {
                int brow = wn * 64 + ni * 8 + (lane & 7);
                int bcol = kk + ((lane >> 3) & 1) * 8;
                uint32_t off = (uint32_t)(brow * SSTR + bcol) * 2;
                uint32_t bhi[2], blo[2];
                ldsm2(bhi, bHiB + off);
                ldsm2(blo, bLoB + off);
#pragma unroll
                for (int mi = 0; mi < 2; mi++) {
                    mma16816(acc[mi][ni], ahi[mi], bhi);
                    mma16816(acc[mi][ni], ahi[mi], blo);
                    mma16816(acc[mi][ni], alo[mi], bhi);
                }
            }
        }
        __syncthreads();
    }

    // ---- epilogue: bias + relu, float2 stores
#pragma unroll
    for (int mi = 0; mi < 2; mi++) {
        int row0 = rowBase + wm * 32 + mi * 16 + (lane >> 2);
        int row1 = row0 + 8;
#pragma unroll
        for (int ni = 0; ni < 8; ni++) {
            int col = colBase + wn * 64 + ni * 8 + (lane & 3) * 2;
            float b0 = bias[col], b1 = bias[col + 1];
            if (row0 < M) {
                float2 v;
                v.x = fmaxf(acc[mi][ni][0] + b0, 0.f);
                v.y = fmaxf(acc[mi][ni][1] + b1, 0.f);
                *(float2*)&C[(size_t)row0 * D + col] = v;
            }
            if (row1 < M) {
                float2 v;
                v.x = fmaxf(acc[mi][ni][2] + b0, 0.f);
                v.y = fmaxf(acc[mi][ni][3] + b1, 0.f);
                *(float2*)&C[(size_t)row1 * D + col] = v;
            }
        }
    }
}

// ---------------------------------------------------------------------------
// BatchNorm
// ---------------------------------------------------------------------------
__global__ void k_bnstats(const float* __restrict__ h) {
    const int ROWS_PER = 200;
    int r0 = blockIdx.x * ROWS_PER;
    int c1 = threadIdx.x;
    int c2 = threadIdx.x + 256;
    float s1 = 0.f, q1 = 0.f, s2 = 0.f, q2 = 0.f;
    int rend = min(r0 + ROWS_PER, N_NODES);
    for (int r = r0; r < rend; r++) {
        float a = h[r * D + c1];
        float b = h[r * D + c2];
        s1 += a; q1 += a * a;
        s2 += b; q2 += b * b;
    }
    atomicAdd(&g_bnsum[c1], s1); atomicAdd(&g_bnsq[c1], q1);
    atomicAdd(&g_bnsum[c2], s2); atomicAdd(&g_bnsq[c2], q2);
}

__global__ void k_bnapply(float* __restrict__ h,
                          const float* __restrict__ gamma, const float* __restrict__ beta) {
    int idx = blockIdx.x * blockDim.x + threadIdx.x;
    if (idx >= N_NODES * D) return;
    int c = idx & (D - 1);
    const float invN = 1.0f / N_NODES;
    float mean = g_bnsum[c] * invN;
    float var = g_bnsq[c] * invN - mean * mean;
    float sc = gamma[c] * rsqrtf(var + BN_EPS);
    h[idx] = (h[idx] - mean) * sc + beta[c];
}

// ---------------------------------------------------------------------------
// Pool + head
// ---------------------------------------------------------------------------
__global__ void k_poolscatter(const float* __restrict__ h, const int* __restrict__ batch) {
    int idx = blockIdx.x * blockDim.x + threadIdx.x;
    if (idx >= N_NODES * (D / 4)) return;
    int n = idx >> 7;
    int g = (idx & 127) << 2;
    int b = batch[n];
    float4 v = *(const float4*)&h[n * D + g];
    red_add_v4(&g_pool[b * D + g], v);
}
__global__ void k_count(const int* __restrict__ batch) {
    int n = blockIdx.x * blockDim.x + threadIdx.x;
    if (n < N_NODES) atomicAdd(&g_cnt[batch[n]], 1.0f);
}
__global__ void k_head(const float* __restrict__ Wfc, const float* __restrict__ bfc,
                       const float* __restrict__ Wlog, const float* __restrict__ blog,
                       float* __restrict__ out) {
    __shared__ float sp[D];
    __shared__ float sf[D];
    int g = blockIdx.x;
    int t = threadIdx.x;
    float invc = 1.0f / fmaxf(g_cnt[g], 1.0f);
    sp[t] = g_pool[g * D + t] * invc;
    __syncthreads();
    float f = bfc[t];
    for (int k = 0; k < D; k++) f += sp[k] * Wfc[k * D + t];
    sf[t] = tanhf(f);
    __syncthreads();
    if (t < N_OUT) {
        float l = blog[t];
        for (int k = 0; k < D; k++) l += sf[k] * Wlog[k * N_OUT + t];
        out[g * N_OUT + t] = l;
    }
}

// ---------------------------------------------------------------------------
// Launcher
// ---------------------------------------------------------------------------
extern "C" void kernel_launch(void* const* d_in, const int* in_sizes, int n_in,
                              void* d_out, int out_size) {
    const float* x     = (const float*)d_in[0];
    const int*   ei    = (const int*)d_in[1];
    const int*   batch = (const int*)d_in[2];
    const float* W1a   = (const float*)d_in[3];
    const float* b1a   = (const float*)d_in[4];
    const float* W1b   = (const float*)d_in[5];
    const float* b1b   = (const float*)d_in[6];
    const float* Wa    = (const float*)d_in[7];
    const float* ba    = (const float*)d_in[8];
    const float* Wb    = (const float*)d_in[9];
    const float* bb    = (const float*)d_in[10];
    const float* bn_g  = (const float*)d_in[11];
    const float* bn_b  = (const float*)d_in[12];
    const float* Wfc   = (const float*)d_in[13];
    const float* bfc   = (const float*)d_in[14];
    const float* Wlog  = (const float*)d_in[15];
    const float* blog  = (const float*)d_in[16];
    float* out = (float*)d_out;

    const int* src = ei;
    const int* dst = ei + N_EDGES;

    float *h, *t, *agg, *agg16;
    __nv_bfloat16 *whi, *wlo;
    cudaGetSymbolAddress((void**)&h,     g_h);
    cudaGetSymbolAddress((void**)&t,     g_t);
    cudaGetSymbolAddress((void**)&agg,   g_agg);
    cudaGetSymbolAddress((void**)&agg16, g_agg16);
    cudaGetSymbolAddress((void**)&whi,   g_Whi);
    cudaGetSymbolAddress((void**)&wlo,   g_Wlo);

    cudaFuncSetAttribute(k_gemm512_mma, cudaFuncAttributeMaxDynamicSharedMemorySize, GEMM_SMEM);

    const int TB = 256;
    dim3 gemmGrid((N_NODES + BM - 1) / BM, D / BN);
    const size_t DD = (size_t)D * D;

    // weight pre-convert (independent of data flow)
    k_convW<<<dim3(16, 16, 9), dim3(32, 8)>>>(W1b, Wa, Wb);

    // ---- layer 1 ----
    k_copy4<<<(N_NODES * IN_F / 4 + TB - 1) / TB, TB>>>(agg16, x, N_NODES * IN_F / 4);
    k_scatter16<<<(N_EDGES * 4 + TB - 1) / TB, TB>>>(x, src, dst);
    k_gemm16<<<(N_NODES * 128 + TB - 1) / TB, TB>>>(W1a, b1a, t);
    k_gemm512_mma<<<gemmGrid, TB, GEMM_SMEM>>>(t, whi, wlo, b1b, h, N_NODES);
    k_zero_bn<<<2, 256>>>();
    k_bnstats<<<50, 256>>>(h);
    k_bnapply<<<(N_NODES * D + TB - 1) / TB, TB>>>(h, bn_g, bn_b);

    // ---- layers 2..5 ----
    for (int i = 0; i < 4; i++) {
        k_copy4<<<(N_NODES * D / 4 + TB - 1) / TB, TB>>>(agg, h, N_NODES * D / 4);
        k_scatter512<<<(N_EDGES * 128 + TB - 1) / TB, TB>>>(h, agg, src, dst);
        k_gemm512_mma<<<gemmGrid, TB, GEMM_SMEM>>>(agg, whi + (size_t)(1 + 2 * i) * DD,
                                                   wlo + (size_t)(1 + 2 * i) * DD,
                                                   ba + i * D, t, N_NODES);
        k_gemm512_mma<<<gemmGrid, TB, GEMM_SMEM>>>(t, whi + (size_t)(2 + 2 * i) * DD,
                                                   wlo + (size_t)(2 + 2 * i) * DD,
                                                   bb + i * D, h, N_NODES);
        k_zero_bn<<<2, 256>>>();
        k_bnstats<<<50, 256>>>(h);
        k_bnapply<<<(N_NODES * D + TB - 1) / TB, TB>>>(h, bn_g + (i + 1) * D, bn_b + (i + 1) * D);
    }

    // ---- pooling + head ----
    k_zero_pool<<<(N_GRAPHS * D + TB - 1) / TB, TB>>>();
    k_poolscatter<<<(N_NODES * 128 + TB - 1) / TB, TB>>>(h, batch);
    k_count<<<(N_NODES + TB - 1) / TB, TB>>>(batch);
    k_head<<<N_GRAPHS, D>>>(Wfc, bfc, Wlog, blog, out);
}

// round 5
// speedup vs baseline: 1.7538x; 1.0732x over previous
#include <cuda_runtime.h>
#include <cuda_bf16.h>
#include <stdint.h>
#include <math.h>

#define N_NODES 10000
#define N_EDGES 160000
#define IN_F    16
#define D       512
#define N_GRAPHS 64
#define N_OUT   18
#define BN_EPS  1e-5f

// ---------------------------------------------------------------------------
// Scratch
// ---------------------------------------------------------------------------
__device__ float g_h[N_NODES * D];
__device__ float g_agg[N_NODES * D];
__device__ float g_agg16[N_NODES * IN_F];
__device__ __nv_bfloat16 g_tHi[N_NODES * D];
__device__ __nv_bfloat16 g_tLo[N_NODES * D];
__device__ __nv_bfloat16 g_aHi[N_NODES * D];
__device__ __nv_bfloat16 g_aLo[N_NODES * D];
__device__ float g_bnsum[D];
__device__ float g_bnsq[D];
__device__ float g_pool[N_GRAPHS * D];
__device__ float g_cnt[N_GRAPHS];
// pre-converted, transposed weights: Bt[n][k] = W[k][n], split hi/lo bf16
__device__ __nv_bfloat16 g_Whi[9 * D * D];
__device__ __nv_bfloat16 g_Wlo[9 * D * D];

typedef unsigned long long ull;

__device__ __forceinline__ void red_add_v4(float* p, float4 v) {
    asm volatile("red.global.add.v4.f32 [%0], {%1,%2,%3,%4};"
                 :: "l"(p), "f"(v.x), "f"(v.y), "f"(v.z), "f"(v.w) : "memory");
}
__device__ __forceinline__ uint32_t smem_u32(const void* p) {
    uint32_t a;
    asm("{ .reg .u64 t; cvta.to.shared.u64 t, %1; cvt.u32.u64 %0, t; }" : "=r"(a) : "l"(p));
    return a;
}
__device__ __forceinline__ void ldsm4(uint32_t* r, uint32_t p) {
    asm volatile("ldmatrix.sync.aligned.m8n8.x4.shared.b16 {%0,%1,%2,%3}, [%4];"
                 : "=r"(r[0]), "=r"(r[1]), "=r"(r[2]), "=r"(r[3]) : "r"(p));
}
__device__ __forceinline__ void ldsm2(uint32_t* r, uint32_t p) {
    asm volatile("ldmatrix.sync.aligned.m8n8.x2.shared.b16 {%0,%1}, [%2];"
                 : "=r"(r[0]), "=r"(r[1]) : "r"(p));
}
__device__ __forceinline__ void mma16816(float* d, const uint32_t* a, const uint32_t* b) {
    asm volatile(
        "mma.sync.aligned.m16n8k16.row.col.f32.bf16.bf16.f32 "
        "{%0,%1,%2,%3}, {%4,%5,%6,%7}, {%8,%9}, {%0,%1,%2,%3};"
        : "+f"(d[0]), "+f"(d[1]), "+f"(d[2]), "+f"(d[3])
        : "r"(a[0]), "r"(a[1]), "r"(a[2]), "r"(a[3]), "r"(b[0]), "r"(b[1]));
}
__device__ __forceinline__ void cpasync16(uint32_t dst, const void* src, int validsz) {
    asm volatile("cp.async.ca.shared.global [%0], [%1], 16, %2;"
                 :: "r"(dst), "l"(src), "r"(validsz));
}
__device__ __forceinline__ void cp_commit() {
    asm volatile("cp.async.commit_group;" ::: "memory");
}
__device__ __forceinline__ void cp_wait1() {
    asm volatile("cp.async.wait_group 1;" ::: "memory");
}
__device__ __forceinline__ void cp_wait0() {
    asm volatile("cp.async.wait_group 0;" ::: "memory");
}
__device__ __forceinline__ uint32_t pack_bf2(float x, float y) {
    __nv_bfloat162 v = __floats2bfloat162_rn(x, y);  // not split-safe; use explicit
    return *(uint32_t*)&v;
}

// ---------------------------------------------------------------------------
// Utility kernels
// ---------------------------------------------------------------------------
__global__ void k_copy4(float* __restrict__ dst, const float* __restrict__ src, int n4) {
    int i = blockIdx.x * blockDim.x + threadIdx.x;
    if (i < n4) ((float4*)dst)[i] = ((const float4*)src)[i];
}
__global__ void k_zero_bn() {
    int i = blockIdx.x * blockDim.x + threadIdx.x;
    if (i < D) { g_bnsum[i] = 0.f; g_bnsq[i] = 0.f; }
}
__global__ void k_zero_pool() {
    int i = blockIdx.x * blockDim.x + threadIdx.x;
    if (i < N_GRAPHS * D) g_pool[i] = 0.f;
    if (i < N_GRAPHS) g_cnt[i] = 0.f;
}

// split f32 -> hi/lo bf16
__global__ void k_convA(const float* __restrict__ A,
                        __nv_bfloat16* __restrict__ Hi, __nv_bfloat16* __restrict__ Lo) {
    int i = blockIdx.x * blockDim.x + threadIdx.x;
    if (i >= N_NODES * D / 4) return;
    float4 v = ((const float4*)A)[i];
    __nv_bfloat16 h0 = __float2bfloat16(v.x), h1 = __float2bfloat16(v.y);
    __nv_bfloat16 h2 = __float2bfloat16(v.z), h3 = __float2bfloat16(v.w);
    __nv_bfloat16 l0 = __float2bfloat16(v.x - __bfloat162float(h0));
    __nv_bfloat16 l1 = __float2bfloat16(v.y - __bfloat162float(h1));
    __nv_bfloat16 l2 = __float2bfloat16(v.z - __bfloat162float(h2));
    __nv_bfloat16 l3 = __float2bfloat16(v.w - __bfloat162float(h3));
    ull ph = (ull)__bfloat16_as_ushort(h0) | ((ull)__bfloat16_as_ushort(h1) << 16)
           | ((ull)__bfloat16_as_ushort(h2) << 32) | ((ull)__bfloat16_as_ushort(h3) << 48);
    ull pl = (ull)__bfloat16_as_ushort(l0) | ((ull)__bfloat16_as_ushort(l1) << 16)
           | ((ull)__bfloat16_as_ushort(l2) << 32) | ((ull)__bfloat16_as_ushort(l3) << 48);
    ((ull*)Hi)[i] = ph;
    ((ull*)Lo)[i] = pl;
}

// Weight convert + transpose: out[m][n][k] = split(W_m[k][n])
__global__ void k_convW(const float* __restrict__ W1b, const float* __restrict__ Wa,
                        const float* __restrict__ Wb) {
    __shared__ float tile[32][33];
    int m = blockIdx.z;
    const float* W = (m == 0) ? W1b
                   : ((m & 1) ? Wa + (size_t)((m - 1) >> 1) * D * D
                              : Wb + (size_t)((m - 2) >> 1) * D * D);
    int tx = threadIdx.x, ty = threadIdx.y;
    int n0 = blockIdx.x * 32, k0 = blockIdx.y * 32;
#pragma unroll
    for (int j = 0; j < 32; j += 8)
        tile[ty + j][tx] = W[(k0 + ty + j) * D + n0 + tx];
    __syncthreads();
#pragma unroll
    for (int j = 0; j < 32; j += 8) {
        float v = tile[tx][ty + j];
        int n = n0 + ty + j, k = k0 + tx;
        __nv_bfloat16 hi = __float2bfloat16(v);
        __nv_bfloat16 lo = __float2bfloat16(v - __bfloat162float(hi));
        size_t o = (size_t)m * D * D + (size_t)n * D + k;
        g_Whi[o] = hi;
        g_Wlo[o] = lo;
    }
}

// ---------------------------------------------------------------------------
// Layer-1 aggregation + small GEMM (IN_F=16), writes split bf16 + relu
// ---------------------------------------------------------------------------
__global__ void k_scatter16(const float* __restrict__ x,
                            const int* __restrict__ src, const int* __restrict__ dst) {
    int idx = blockIdx.x * blockDim.x + threadIdx.x;
    if (idx >= N_EDGES * 4) return;
    int e = idx >> 2;
    int g = (idx & 3) << 2;
    int s = src[e], d = dst[e];
    float4 v = *(const float4*)&x[s * IN_F + g];
    red_add_v4(&g_agg16[d * IN_F + g], v);
}

__global__ void k_gemm16(const float* __restrict__ W, const float* __restrict__ bias) {
    int idx = blockIdx.x * blockDim.x + threadIdx.x;
    if (idx >= N_NODES * (D / 4)) return;
    int n = idx >> 7;
    int c = (idx & 127) << 2;
    float4 acc = *(const float4*)&bias[c];
    const float* arow = &g_agg16[n * IN_F];
#pragma unroll
    for (int k = 0; k < IN_F; k++) {
        float a = arow[k];
        float4 w = *(const float4*)&W[k * D + c];
        acc.x += a * w.x; acc.y += a * w.y; acc.z += a * w.z; acc.w += a * w.w;
    }
    acc.x = fmaxf(acc.x, 0.f); acc.y = fmaxf(acc.y, 0.f);
    acc.z = fmaxf(acc.z, 0.f); acc.w = fmaxf(acc.w, 0.f);
    __nv_bfloat16 h0 = __float2bfloat16(acc.x), h1 = __float2bfloat16(acc.y);
    __nv_bfloat16 h2 = __float2bfloat16(acc.z), h3 = __float2bfloat16(acc.w);
    __nv_bfloat16 l0 = __float2bfloat16(acc.x - __bfloat162float(h0));
    __nv_bfloat16 l1 = __float2bfloat16(acc.y - __bfloat162float(h1));
    __nv_bfloat16 l2 = __float2bfloat16(acc.z - __bfloat162float(h2));
    __nv_bfloat16 l3 = __float2bfloat16(acc.w - __bfloat162float(h3));
    ull ph = (ull)__bfloat16_as_ushort(h0) | ((ull)__bfloat16_as_ushort(h1) << 16)
           | ((ull)__bfloat16_as_ushort(h2) << 32) | ((ull)__bfloat16_as_ushort(h3) << 48);
    ull pl = (ull)__bfloat16_as_ushort(l0) | ((ull)__bfloat16_as_ushort(l1) << 16)
           | ((ull)__bfloat16_as_ushort(l2) << 32) | ((ull)__bfloat16_as_ushort(l3) << 48);
    *(ull*)&g_tHi[n * D + c] = ph;
    *(ull*)&g_tLo[n * D + c] = pl;
}

// ---------------------------------------------------------------------------
// D=512 aggregation
// ---------------------------------------------------------------------------
__global__ void k_scatter512(const float* __restrict__ hfeat, float* __restrict__ agg,
                             const int* __restrict__ src, const int* __restrict__ dst) {
    long long idx = (long long)blockIdx.x * blockDim.x + threadIdx.x;
    if (idx >= (long long)N_EDGES * (D / 4)) return;
    int e = (int)(idx >> 7);
    int g = ((int)idx & 127) << 2;
    int s = src[e], d = dst[e];
    float4 v = *(const float4*)&hfeat[s * D + g];
    red_add_v4(&agg[d * D + g], v);
}

// ---------------------------------------------------------------------------
// HMMA GEMM, all-bf16 inputs, cp.async double-buffered.
// BM=128, BN=128, BK=32; 8 warps (4 M x 2 N), warp tile 32x64.
// 3-term split: Ahi*Bhi + Ahi*Blo + Alo*Bhi, fp32 accum.
// mode 0: out f32 (Cf);  mode 1: out split bf16 (Chi/Clo). Both apply relu.
// ---------------------------------------------------------------------------
#define BM 128
#define BN 128
#define BK 32
#define SSTR 40                        // padded smem row stride (bf16)
#define ARR_B (128 * SSTR * 2)         // 10240 bytes per array
#define STG_B (4 * ARR_B)              // 40960 bytes per stage
#define GEMM_SMEM (2 * STG_B)          // 81920 bytes

__global__ __launch_bounds__(256, 2)
void k_gemm512_mma(const __nv_bfloat16* __restrict__ Ahi,
                   const __nv_bfloat16* __restrict__ Alo,
                   const __nv_bfloat16* __restrict__ Bthi,
                   const __nv_bfloat16* __restrict__ Btlo,
                   const float* __restrict__ bias,
                   float* __restrict__ Cf,
                   __nv_bfloat16* __restrict__ Chi,
                   __nv_bfloat16* __restrict__ Clo,
                   int M, int mode) {
    extern __shared__ char sm[];
    const uint32_t sbase = smem_u32(sm);

    const int tid = threadIdx.x;
    const int lane = tid & 31;
    const int warp = tid >> 5;
    const int wm = warp & 3;
    const int wn = warp >> 2;
    const int rowBase = blockIdx.x * BM;
    const int colBase = blockIdx.y * BN;

    // per-thread producer coords: 2 chunks per array
    const int r0 = tid >> 2,       c0 = tid & 3;         // chunk 0 (rows 0..63)
    const int r1 = (tid + 256) >> 2, c1 = tid & 3;       // chunk 1 (rows 64..127)
    const int av0 = (rowBase + r0 < M) ? 16 : 0;
    const int av1 = (rowBase + r1 < M) ? 16 : 0;

    float acc[2][8][4];
#pragma unroll
    for (int mi = 0; mi < 2; mi++)
#pragma unroll
        for (int ni = 0; ni < 8; ni++)
#pragma unroll
            for (int j = 0; j < 4; j++) acc[mi][ni][j] = 0.f;

#define PREFETCH(kc_, s_)                                                          \
    {                                                                              \
        const int k0_ = (kc_) * BK;                                                \
        const uint32_t sb_ = sbase + (s_) * STG_B;                                 \
        cpasync16(sb_ + 0 * ARR_B + (r0 * SSTR + c0 * 8) * 2,                      \
                  &Ahi[(size_t)(rowBase + r0) * D + k0_ + c0 * 8], av0);           \
        cpasync16(sb_ + 0 * ARR_B + (r1 * SSTR + c1 * 8) * 2,                      \
                  &Ahi[(size_t)(rowBase + r1) * D + k0_ + c1 * 8], av1);           \
        cpasync16(sb_ + 1 * ARR_B + (r0 * SSTR + c0 * 8) * 2,                      \
                  &Alo[(size_t)(rowBase + r0) * D + k0_ + c0 * 8], av0);           \
        cpasync16(sb_ + 1 * ARR_B + (r1 * SSTR + c1 * 8) * 2,                      \
                  &Alo[(size_t)(rowBase + r1) * D + k0_ + c1 * 8], av1);           \
        cpasync16(sb_ + 2 * ARR_B + (r0 * SSTR + c0 * 8) * 2,                      \
                  &Bthi[(size_t)(colBase + r0) * D + k0_ + c0 * 8], 16);           \
        cpasync16(sb_ + 2 * ARR_B + (r1 * SSTR + c1 * 8) * 2,                      \
                  &Bthi[(size_t)(colBase + r1) * D + k0_ + c1 * 8], 16);           \
        cpasync16(sb_ + 3 * ARR_B + (r0 * SSTR + c0 * 8) * 2,                      \
                  &Btlo[(size_t)(colBase + r0) * D + k0_ + c0 * 8], 16);           \
        cpasync16(sb_ + 3 * ARR_B + (r1 * SSTR + c1 * 8) * 2,                      \
                  &Btlo[(size_t)(colBase + r1) * D + k0_ + c1 * 8], 16);           \
        cp_commit();                                                               \
    }

    PREFETCH(0, 0);

    for (int kc = 0; kc < D / BK; kc++) {
        const int s = kc & 1;
        if (kc + 1 < D / BK) {
            PREFETCH(kc + 1, s ^ 1);
            cp_wait1();
        } else {
            cp_wait0();
        }
        __syncthreads();

        const uint32_t sb = sbase + s * STG_B;
        const uint32_t aHiB = sb, aLoB = sb + ARR_B, bHiB = sb + 2 * ARR_B, bLoB = sb + 3 * ARR_B;

#pragma unroll
        for (int ks = 0; ks < 2; ks++) {
            const int kk = ks * 16;
            uint32_t ahi[2][4], alo[2][4];
#pragma unroll
            for (int mi = 0; mi < 2; mi++) {
                int row = wm * 32 + mi * 16 + (lane & 15);
                int col = kk + (lane >> 4) * 8;
                uint32_t off = (uint32_t)(row * SSTR + col) * 2;
                ldsm4(ahi[mi], aHiB + off);
                ldsm4(alo[mi], aLoB + off);
            }
#pragma unroll
            for (int ni = 0; ni < 8; ni++) {
                int brow = wn * 64 + ni * 8 + (lane & 7);
                int bcol = kk + ((lane >> 3) & 1) * 8;
                uint32_t off = (uint32_t)(brow * SSTR + bcol) * 2;
                uint32_t bhi[2], blo[2];
                ldsm2(bhi, bHiB + off);
                ldsm2(blo, bLoB + off);
#pragma unroll
                for (int mi = 0; mi < 2; mi++) {
                    mma16816(acc[mi][ni], ahi[mi], bhi);
                    mma16816(acc[mi][ni], ahi[mi], blo);
                    mma16816(acc[mi][ni], alo[mi], bhi);
                }
            }
        }
        __syncthreads();
    }
#undef PREFETCH

    // ---- epilogue: bias + relu
#pragma unroll
    for (int mi = 0; mi < 2; mi++) {
        int row0 = rowBase + wm * 32 + mi * 16 + (lane >> 2);
        int row1 = row0 + 8;
#pragma unroll
        for (int ni = 0; ni < 8; ni++) {
            int col = colBase + wn * 64 + ni * 8 + (lane & 3) * 2;
            float b0 = bias[col], b1 = bias[col + 1];
            float v00 = fmaxf(acc[mi][ni][0] + b0, 0.f);
            float v01 = fmaxf(acc[mi][ni][1] + b1, 0.f);
            float v10 = fmaxf(acc[mi][ni][2] + b0, 0.f);
            float v11 = fmaxf(acc[mi][ni][3] + b1, 0.f);
            if (mode == 0) {
                if (row0 < M) *(float2*)&Cf[(size_t)row0 * D + col] = make_float2(v00, v01);
                if (row1 < M) *(float2*)&Cf[(size_t)row1 * D + col] = make_float2(v10, v11);
            } else {
                __nv_bfloat16 h0 = __float2bfloat16(v00), h1 = __float2bfloat16(v01);
                __nv_bfloat16 h2 = __float2bfloat16(v10), h3 = __float2bfloat16(v11);
                __nv_bfloat16 l0 = __float2bfloat16(v00 - __bfloat162float(h0));
                __nv_bfloat16 l1 = __float2bfloat16(v01 - __bfloat162float(h1));
                __nv_bfloat16 l2 = __float2bfloat16(v10 - __bfloat162float(h2));
                __nv_bfloat16 l3 = __float2bfloat16(v11 - __bfloat162float(h3));
                if (row0 < M) {
                    *(uint32_t*)&Chi[(size_t)row0 * D + col] =
                        (uint32_t)__bfloat16_as_ushort(h0) | ((uint32_t)__bfloat16_as_ushort(h1) << 16);
                    *(uint32_t*)&Clo[(size_t)row0 * D + col] =
                        (uint32_t)__bfloat16_as_ushort(l0) | ((uint32_t)__bfloat16_as_ushort(l1) << 16);
                }
                if (row1 < M) {
                    *(uint32_t*)&Chi[(size_t)row1 * D + col] =
                        (uint32_t)__bfloat16_as_ushort(h2) | ((uint32_t)__bfloat16_as_ushort(h3) << 16);
                    *(uint32_t*)&Clo[(size_t)row1 * D + col] =
                        (uint32_t)__bfloat16_as_ushort(l2) | ((uint32_t)__bfloat16_as_ushort(l3) << 16);
                }
            }
        }
    }
}

// ---------------------------------------------------------------------------
// BatchNorm
// ---------------------------------------------------------------------------
__global__ void k_bnstats(const float* __restrict__ h) {
    const int ROWS_PER = 200;
    int r0 = blockIdx.x * ROWS_PER;
    int c1 = threadIdx.x;
    int c2 = threadIdx.x + 256;
    float s1 = 0.f, q1 = 0.f, s2 = 0.f, q2 = 0.f;
    int rend = min(r0 + ROWS_PER, N_NODES);
    for (int r = r0; r < rend; r++) {
        float a = h[r * D + c1];
        float b = h[r * D + c2];
        s1 += a; q1 += a * a;
        s2 += b; q2 += b * b;
    }
    atomicAdd(&g_bnsum[c1], s1); atomicAdd(&g_bnsq[c1], q1);
    atomicAdd(&g_bnsum[c2], s2); atomicAdd(&g_bnsq[c2], q2);
}

// applies BN in place; optionally also writes agg = normalized h (init for scatter)
__global__ void k_bnapply(float* __restrict__ h, float* __restrict__ agg,
                          const float* __restrict__ gamma, const float* __restrict__ beta,
                          int writeAgg) {
    int idx = blockIdx.x * blockDim.x + threadIdx.x;
    if (idx >= N_NODES * D) return;
    int c = idx & (D - 1);
    const float invN = 1.0f / N_NODES;
    float mean = g_bnsum[c] * invN;
    float var = g_bnsq[c] * invN - mean * mean;
    float sc = gamma[c] * rsqrtf(var + BN_EPS);
    float v = (h[idx] - mean) * sc + beta[c];
    h[idx] = v;
    if (writeAgg) agg[idx] = v;
}

// ---------------------------------------------------------------------------
// Pool + head
// ---------------------------------------------------------------------------
__global__ void k_poolscatter(const float* __restrict__ h, const int* __restrict__ batch) {
    int idx = blockIdx.x * blockDim.x + threadIdx.x;
    if (idx >= N_NODES * (D / 4)) return;
    int n = idx >> 7;
    int g = (idx & 127) << 2;
    int b = batch[n];
    float4 v = *(const float4*)&h[n * D + g];
    red_add_v4(&g_pool[b * D + g], v);
}
__global__ void k_count(const int* __restrict__ batch) {
    int n = blockIdx.x * blockDim.x + threadIdx.x;
    if (n < N_NODES) atomicAdd(&g_cnt[batch[n]], 1.0f);
}
__global__ void k_head(const float* __restrict__ Wfc, const float* __restrict__ bfc,
                       const float* __restrict__ Wlog, const float* __restrict__ blog,
                       float* __restrict__ out) {
    __shared__ float sp[D];
    __shared__ float sf[D];
    int g = blockIdx.x;
    int t = threadIdx.x;
    float invc = 1.0f / fmaxf(g_cnt[g], 1.0f);
    sp[t] = g_pool[g * D + t] * invc;
    __syncthreads();
    float f = bfc[t];
    for (int k = 0; k < D; k++) f += sp[k] * Wfc[k * D + t];
    sf[t] = tanhf(f);
    __syncthreads();
    if (t < N_OUT) {
        float l = blog[t];
        for (int k = 0; k < D; k++) l += sf[k] * Wlog[k * N_OUT + t];
        out[g * N_OUT + t] = l;
    }
}

// ---------------------------------------------------------------------------
// Launcher
// ---------------------------------------------------------------------------
extern "C" void kernel_launch(void* const* d_in, const int* in_sizes, int n_in,
                              void* d_out, int out_size) {
    const float* x     = (const float*)d_in[0];
    const int*   ei    = (const int*)d_in[1];
    const int*   batch = (const int*)d_in[2];
    const float* W1a   = (const float*)d_in[3];
    const float* b1a   = (const float*)d_in[4];
    const float* W1b   = (const float*)d_in[5];
    const float* b1b   = (const float*)d_in[6];
    const float* Wa    = (const float*)d_in[7];
    const float* ba    = (const float*)d_in[8];
    const float* Wb    = (const float*)d_in[9];
    const float* bb    = (const float*)d_in[10];
    const float* bn_g  = (const float*)d_in[11];
    const float* bn_b  = (const float*)d_in[12];
    const float* Wfc   = (const float*)d_in[13];
    const float* bfc   = (const float*)d_in[14];
    const float* Wlog  = (const float*)d_in[15];
    const float* blog  = (const float*)d_in[16];
    float* out = (float*)d_out;

    const int* src = ei;
    const int* dst = ei + N_EDGES;

    float *h, *agg, *agg16;
    __nv_bfloat16 *whi, *wlo, *thi, *tlo, *ahi, *alo;
    cudaGetSymbolAddress((void**)&h,     g_h);
    cudaGetSymbolAddress((void**)&agg,   g_agg);
    cudaGetSymbolAddress((void**)&agg16, g_agg16);
    cudaGetSymbolAddress((void**)&whi,   g_Whi);
    cudaGetSymbolAddress((void**)&wlo,   g_Wlo);
    cudaGetSymbolAddress((void**)&thi,   g_tHi);
    cudaGetSymbolAddress((void**)&tlo,   g_tLo);
    cudaGetSymbolAddress((void**)&ahi,   g_aHi);
    cudaGetSymbolAddress((void**)&alo,   g_aLo);

    cudaFuncSetAttribute(k_gemm512_mma, cudaFuncAttributeMaxDynamicSharedMemorySize, GEMM_SMEM);

    const int TB = 256;
    dim3 gemmGrid((N_NODES + BM - 1) / BM, D / BN);
    const size_t DD = (size_t)D * D;
    const int n4 = N_NODES * D / 4;

    // weight pre-convert
    k_convW<<<dim3(16, 16, 9), dim3(32, 8)>>>(W1b, Wa, Wb);

    // ---- layer 1 ----
    k_copy4<<<(N_NODES * IN_F / 4 + TB - 1) / TB, TB>>>(agg16, x, N_NODES * IN_F / 4);
    k_scatter16<<<(N_EDGES * 4 + TB - 1) / TB, TB>>>(x, src, dst);
    k_gemm16<<<(N_NODES * 128 + TB - 1) / TB, TB>>>(W1a, b1a);
    k_gemm512_mma<<<gemmGrid, TB, GEMM_SMEM>>>(thi, tlo, whi, wlo, b1b, h,
                                               ((__nv_bfloat16*)0), ((__nv_bfloat16*)0),
                                               N_NODES, 0);
    k_zero_bn<<<2, 256>>>();
    k_bnstats<<<50, 256>>>(h);
    k_bnapply<<<(N_NODES * D + TB - 1) / TB, TB>>>(h, agg, bn_g, bn_b, 1);

    // ---- layers 2..5 ----
    for (int i = 0; i < 4; i++) {
        k_scatter512<<<(N_EDGES * 128 + TB - 1) / TB, TB>>>(h, agg, src, dst);
        k_convA<<<(n4 + TB - 1) / TB, TB>>>(agg, ahi, alo);
        k_gemm512_mma<<<gemmGrid, TB, GEMM_SMEM>>>(ahi, alo,
                                                   whi + (size_t)(1 + 2 * i) * DD,
                                                   wlo + (size_t)(1 + 2 * i) * DD,
                                                   ba + i * D, ((float*)0), thi, tlo,
                                                   N_NODES, 1);
        k_gemm512_mma<<<gemmGrid, TB, GEMM_SMEM>>>(thi, tlo,
                                                   whi + (size_t)(2 + 2 * i) * DD,
                                                   wlo + (size_t)(2 + 2 * i) * DD,
                                                   bb + i * D, h,
                                                   ((__nv_bfloat16*)0), ((__nv_bfloat16*)0),
                                                   N_NODES, 0);
        k_zero_bn<<<2, 256>>>();
        k_bnstats<<<50, 256>>>(h);
        k_bnapply<<<(N_NODES * D + TB - 1) / TB, TB>>>(h, agg, bn_g + (i + 1) * D,
                                                       bn_b + (i + 1) * D, i < 3 ? 1 : 0);
    }

    // ---- pooling + head ----
    k_zero_pool<<<(N_GRAPHS * D + TB - 1) / TB, TB>>>();
    k_poolscatter<<<(N_NODES * 128 + TB - 1) / TB, TB>>>(h, batch);
    k_count<<<(N_NODES + TB - 1) / TB, TB>>>(batch);
    k_head<<<N_GRAPHS, D>>>(Wfc, bfc, Wlog, blog, out);
}

// round 6
// speedup vs baseline: 2.3104x; 1.3174x over previous
#include <cuda_runtime.h>
#include <cuda_bf16.h>
#include <stdint.h>
#include <math.h>

#define N_NODES 10000
#define N_EDGES 160000
#define IN_F    16
#define D       512
#define N_GRAPHS 64
#define N_OUT   18
#define BN_EPS  1e-5f

// ---------------------------------------------------------------------------
// Scratch
// ---------------------------------------------------------------------------
__device__ float g_h[N_NODES * D];
__device__ float g_agg16[N_NODES * IN_F];
__device__ __nv_bfloat16 g_tHi[N_NODES * D];
__device__ __nv_bfloat16 g_tLo[N_NODES * D];
__device__ __nv_bfloat16 g_aHi[N_NODES * D];
__device__ __nv_bfloat16 g_aLo[N_NODES * D];
__device__ float g_bnsum[D];
__device__ float g_bnsq[D];
__device__ float g_pool[N_GRAPHS * D];
__device__ float g_cnt[N_GRAPHS];
__device__ __nv_bfloat16 g_Whi[9 * D * D];
__device__ __nv_bfloat16 g_Wlo[9 * D * D];
// CSR
__device__ int g_deg[N_NODES];
__device__ int g_rowptr[N_NODES + 1];
__device__ int g_colidx[N_EDGES];

typedef unsigned long long ull;

__device__ __forceinline__ void red_add_v4(float* p, float4 v) {
    asm volatile("red.global.add.v4.f32 [%0], {%1,%2,%3,%4};"
                 :: "l"(p), "f"(v.x), "f"(v.y), "f"(v.z), "f"(v.w) : "memory");
}
__device__ __forceinline__ uint32_t smem_u32(const void* p) {
    uint32_t a;
    asm("{ .reg .u64 t; cvta.to.shared.u64 t, %1; cvt.u32.u64 %0, t; }" : "=r"(a) : "l"(p));
    return a;
}
__device__ __forceinline__ void ldsm4(uint32_t* r, uint32_t p) {
    asm volatile("ldmatrix.sync.aligned.m8n8.x4.shared.b16 {%0,%1,%2,%3}, [%4];"
                 : "=r"(r[0]), "=r"(r[1]), "=r"(r[2]), "=r"(r[3]) : "r"(p));
}
__device__ __forceinline__ void mma16816(float* d, const uint32_t* a, const uint32_t* b) {
    asm volatile(
        "mma.sync.aligned.m16n8k16.row.col.f32.bf16.bf16.f32 "
        "{%0,%1,%2,%3}, {%4,%5,%6,%7}, {%8,%9}, {%0,%1,%2,%3};"
        : "+f"(d[0]), "+f"(d[1]), "+f"(d[2]), "+f"(d[3])
        : "r"(a[0]), "r"(a[1]), "r"(a[2]), "r"(a[3]), "r"(b[0]), "r"(b[1]));
}
__device__ __forceinline__ void cpasync16(uint32_t dst, const void* src, int validsz) {
    asm volatile("cp.async.ca.shared.global [%0], [%1], 16, %2;"
                 :: "r"(dst), "l"(src), "r"(validsz));
}
__device__ __forceinline__ void cp_commit() { asm volatile("cp.async.commit_group;" ::: "memory"); }
__device__ __forceinline__ void cp_wait1()  { asm volatile("cp.async.wait_group 1;" ::: "memory"); }
__device__ __forceinline__ void cp_wait0()  { asm volatile("cp.async.wait_group 0;" ::: "memory"); }

__device__ __forceinline__ ull split_pack4(float4 v, ull& plo) {
    __nv_bfloat16 h0 = __float2bfloat16(v.x), h1 = __float2bfloat16(v.y);
    __nv_bfloat16 h2 = __float2bfloat16(v.z), h3 = __float2bfloat16(v.w);
    __nv_bfloat16 l0 = __float2bfloat16(v.x - __bfloat162float(h0));
    __nv_bfloat16 l1 = __float2bfloat16(v.y - __bfloat162float(h1));
    __nv_bfloat16 l2 = __float2bfloat16(v.z - __bfloat162float(h2));
    __nv_bfloat16 l3 = __float2bfloat16(v.w - __bfloat162float(h3));
    plo = (ull)__bfloat16_as_ushort(l0) | ((ull)__bfloat16_as_ushort(l1) << 16)
        | ((ull)__bfloat16_as_ushort(l2) << 32) | ((ull)__bfloat16_as_ushort(l3) << 48);
    return (ull)__bfloat16_as_ushort(h0) | ((ull)__bfloat16_as_ushort(h1) << 16)
         | ((ull)__bfloat16_as_ushort(h2) << 32) | ((ull)__bfloat16_as_ushort(h3) << 48);
}

// ---------------------------------------------------------------------------
// Utility kernels
// ---------------------------------------------------------------------------
__global__ void k_copy4(float* __restrict__ dst, const float* __restrict__ src, int n4) {
    int i = blockIdx.x * blockDim.x + threadIdx.x;
    if (i < n4) ((float4*)dst)[i] = ((const float4*)src)[i];
}
__global__ void k_zero_bn() {
    int i = blockIdx.x * blockDim.x + threadIdx.x;
    if (i < D) { g_bnsum[i] = 0.f; g_bnsq[i] = 0.f; }
}
__global__ void k_zero_pool() {
    int i = blockIdx.x * blockDim.x + threadIdx.x;
    if (i < N_GRAPHS * D) g_pool[i] = 0.f;
    if (i < N_GRAPHS) g_cnt[i] = 0.f;
}

// ---------------------------------------------------------------------------
// CSR build
// ---------------------------------------------------------------------------
__global__ void k_zero_deg() {
    int i = blockIdx.x * blockDim.x + threadIdx.x;
    if (i < N_NODES) g_deg[i] = 0;
}
__global__ void k_deg(const int* __restrict__ dst) {
    int e = blockIdx.x * blockDim.x + threadIdx.x;
    if (e < N_EDGES) atomicAdd(&g_deg[dst[e]], 1);
}
__global__ void k_scan() {
    __shared__ int ssum[1024];
    int t = threadIdx.x;
    int base = t * 10;
    int loc[10];
    int s = 0;
#pragma unroll
    for (int i = 0; i < 10; i++) {
        int idx = base + i;
        int v = (idx < N_NODES) ? g_deg[idx] : 0;
        loc[i] = s; s += v;
    }
    ssum[t] = s;
    __syncthreads();
    for (int off = 1; off < 1024; off <<= 1) {
        int add = (t >= off) ? ssum[t - off] : 0;
        __syncthreads();
        ssum[t] += add;
        __syncthreads();
    }
    int excl = ssum[t] - s;
#pragma unroll
    for (int i = 0; i < 10; i++) {
        int idx = base + i;
        if (idx < N_NODES) { g_rowptr[idx] = excl + loc[i]; g_deg[idx] = 0; }
    }
    if (t == 0) g_rowptr[N_NODES] = N_EDGES;
}
__global__ void k_fill(const int* __restrict__ src, const int* __restrict__ dst) {
    int e = blockIdx.x * blockDim.x + threadIdx.x;
    if (e >= N_EDGES) return;
    int d = dst[e];
    int p = atomicAdd(&g_deg[d], 1);
    g_colidx[g_rowptr[d] + p] = src[e];
}

// ---------------------------------------------------------------------------
// Weight convert + transpose: out[m][n][k] = split(W_m[k][n])
// ---------------------------------------------------------------------------
__global__ void k_convW(const float* __restrict__ W1b, const float* __restrict__ Wa,
                        const float* __restrict__ Wb) {
    __shared__ float tile[32][33];
    int m = blockIdx.z;
    const float* W = (m == 0) ? W1b
                   : ((m & 1) ? Wa + (size_t)((m - 1) >> 1) * D * D
                              : Wb + (size_t)((m - 2) >> 1) * D * D);
    int tx = threadIdx.x, ty = threadIdx.y;
    int n0 = blockIdx.x * 32, k0 = blockIdx.y * 32;
#pragma unroll
    for (int j = 0; j < 32; j += 8)
        tile[ty + j][tx] = W[(k0 + ty + j) * D + n0 + tx];
    __syncthreads();
#pragma unroll
    for (int j = 0; j < 32; j += 8) {
        float v = tile[tx][ty + j];
        int n = n0 + ty + j, k = k0 + tx;
        __nv_bfloat16 hi = __float2bfloat16(v);
        __nv_bfloat16 lo = __float2bfloat16(v - __bfloat162float(hi));
        size_t o = (size_t)m * D * D + (size_t)n * D + k;
        g_Whi[o] = hi;
        g_Wlo[o] = lo;
    }
}

// ---------------------------------------------------------------------------
// Layer-1 aggregation + small GEMM (IN_F=16), emits split bf16 + relu
// ---------------------------------------------------------------------------
__global__ void k_scatter16(const float* __restrict__ x,
                            const int* __restrict__ src, const int* __restrict__ dst) {
    int idx = blockIdx.x * blockDim.x + threadIdx.x;
    if (idx >= N_EDGES * 4) return;
    int e = idx >> 2;
    int g = (idx & 3) << 2;
    int s = src[e], d = dst[e];
    float4 v = *(const float4*)&x[s * IN_F + g];
    red_add_v4(&g_agg16[d * IN_F + g], v);
}

__global__ void k_gemm16(const float* __restrict__ W, const float* __restrict__ bias) {
    int idx = blockIdx.x * blockDim.x + threadIdx.x;
    if (idx >= N_NODES * (D / 4)) return;
    int n = idx >> 7;
    int c = (idx & 127) << 2;
    float4 acc = *(const float4*)&bias[c];
    const float* arow = &g_agg16[n * IN_F];
#pragma unroll
    for (int k = 0; k < IN_F; k++) {
        float a = arow[k];
        float4 w = *(const float4*)&W[k * D + c];
        acc.x += a * w.x; acc.y += a * w.y; acc.z += a * w.z; acc.w += a * w.w;
    }
    acc.x = fmaxf(acc.x, 0.f); acc.y = fmaxf(acc.y, 0.f);
    acc.z = fmaxf(acc.z, 0.f); acc.w = fmaxf(acc.w, 0.f);
    ull pl;
    ull ph = split_pack4(acc, pl);
    *(ull*)&g_tHi[n * D + c] = ph;
    *(ull*)&g_tLo[n * D + c] = pl;
}

// ---------------------------------------------------------------------------
// CSR gather + fused BN-apply + hi/lo split.
// out = sc*(h[n]+sum h[src]) + cnt*(beta - sc*mean)  per channel.
// One warp per (node, 128-channel quarter).
// ---------------------------------------------------------------------------
__global__ __launch_bounds__(256)
void k_gather_bn(const float* __restrict__ h,
                 const float* __restrict__ gamma, const float* __restrict__ beta,
                 __nv_bfloat16* __restrict__ Hi, __nv_bfloat16* __restrict__ Lo) {
    int gw = (blockIdx.x * 256 + threadIdx.x) >> 5;
    if (gw >= N_NODES * 4) return;
    int lane = threadIdx.x & 31;
    int n = gw >> 2;
    int c = ((gw & 3) << 7) + lane * 4;

    float4 acc = *(const float4*)&h[(size_t)n * D + c];
    int e0 = g_rowptr[n], e1 = g_rowptr[n + 1];
    int e = e0;
    for (; e + 2 <= e1; e += 2) {
        int s0 = g_colidx[e], s1 = g_colidx[e + 1];
        float4 v0 = *(const float4*)&h[(size_t)s0 * D + c];
        float4 v1 = *(const float4*)&h[(size_t)s1 * D + c];
        acc.x += v0.x + v1.x; acc.y += v0.y + v1.y;
        acc.z += v0.z + v1.z; acc.w += v0.w + v1.w;
    }
    if (e < e1) {
        int s0 = g_colidx[e];
        float4 v0 = *(const float4*)&h[(size_t)s0 * D + c];
        acc.x += v0.x; acc.y += v0.y; acc.z += v0.z; acc.w += v0.w;
    }
    float cnt = (float)(e1 - e0 + 1);
    const float invN = 1.0f / N_NODES;
    float4 bs = *(const float4*)&g_bnsum[c];
    float4 bq = *(const float4*)&g_bnsq[c];
    float4 gm = *(const float4*)&gamma[c];
    float4 bt = *(const float4*)&beta[c];
    float m0 = bs.x * invN, m1 = bs.y * invN, m2 = bs.z * invN, m3 = bs.w * invN;
    float s0 = gm.x * rsqrtf(bq.x * invN - m0 * m0 + BN_EPS);
    float s1 = gm.y * rsqrtf(bq.y * invN - m1 * m1 + BN_EPS);
    float s2 = gm.z * rsqrtf(bq.z * invN - m2 * m2 + BN_EPS);
    float s3 = gm.w * rsqrtf(bq.w * invN - m3 * m3 + BN_EPS);
    float4 o;
    o.x = s0 * acc.x + cnt * (bt.x - s0 * m0);
    o.y = s1 * acc.y + cnt * (bt.y - s1 * m1);
    o.z = s2 * acc.z + cnt * (bt.z - s2 * m2);
    o.w = s3 * acc.w + cnt * (bt.w - s3 * m3);
    ull pl;
    ull ph = split_pack4(o, pl);
    *(ull*)&Hi[(size_t)n * D + c] = ph;
    *(ull*)&Lo[(size_t)n * D + c] = pl;
}

// ---------------------------------------------------------------------------
// HMMA GEMM, all-bf16 inputs, cp.async double-buffered.
// BM=128, BN=128, BK=32; 8 warps (4 M x 2 N), warp tile 32x64.
// 3-term split: Ahi*Bhi + Ahi*Blo + Alo*Bhi, fp32 accum.
// mode 0: out f32 (Cf) + relu; mode 1: out split bf16 (Chi/Clo) + relu.
// ---------------------------------------------------------------------------
#define BM 128
#define BN 128
#define BK 32
#define SSTR 40
#define ARR_B (128 * SSTR * 2)
#define STG_B (4 * ARR_B)
#define GEMM_SMEM (2 * STG_B)

__global__ __launch_bounds__(256, 2)
void k_gemm512_mma(const __nv_bfloat16* __restrict__ Ahi,
                   const __nv_bfloat16* __restrict__ Alo,
                   const __nv_bfloat16* __restrict__ Bthi,
                   const __nv_bfloat16* __restrict__ Btlo,
                   const float* __restrict__ bias,
                   float* __restrict__ Cf,
                   __nv_bfloat16* __restrict__ Chi,
                   __nv_bfloat16* __restrict__ Clo,
                   int M, int mode) {
    extern __shared__ char sm[];
    const uint32_t sbase = smem_u32(sm);

    const int tid = threadIdx.x;
    const int lane = tid & 31;
    const int warp = tid >> 5;
    const int wm = warp & 3;
    const int wn = warp >> 2;
    const int rowBase = blockIdx.x * BM;
    const int colBase = blockIdx.y * BN;

    const int r0 = tid >> 2,         c0 = tid & 3;
    const int r1 = (tid + 256) >> 2, c1 = tid & 3;
    const int av0 = (rowBase + r0 < M) ? 16 : 0;
    const int av1 = (rowBase + r1 < M) ? 16 : 0;

    float acc[2][8][4];
#pragma unroll
    for (int mi = 0; mi < 2; mi++)
#pragma unroll
        for (int ni = 0; ni < 8; ni++)
#pragma unroll
            for (int j = 0; j < 4; j++) acc[mi][ni][j] = 0.f;

#define PREFETCH(kc_, s_)                                                          \
    {                                                                              \
        const int k0_ = (kc_) * BK;                                                \
        const uint32_t sb_ = sbase + (s_) * STG_B;                                 \
        cpasync16(sb_ + 0 * ARR_B + (r0 * SSTR + c0 * 8) * 2,                      \
                  &Ahi[(size_t)(rowBase + r0) * D + k0_ + c0 * 8], av0);           \
        cpasync16(sb_ + 0 * ARR_B + (r1 * SSTR + c1 * 8) * 2,                      \
                  &Ahi[(size_t)(rowBase + r1) * D + k0_ + c1 * 8], av1);           \
        cpasync16(sb_ + 1 * ARR_B + (r0 * SSTR + c0 * 8) * 2,                      \
                  &Alo[(size_t)(rowBase + r0) * D + k0_ + c0 * 8], av0);           \
        cpasync16(sb_ + 1 * ARR_B + (r1 * SSTR + c1 * 8) * 2,                      \
                  &Alo[(size_t)(rowBase + r1) * D + k0_ + c1 * 8], av1);           \
        cpasync16(sb_ + 2 * ARR_B + (r0 * SSTR + c0 * 8) * 2,                      \
                  &Bthi[(size_t)(colBase + r0) * D + k0_ + c0 * 8], 16);           \
        cpasync16(sb_ + 2 * ARR_B + (r1 * SSTR + c1 * 8) * 2,                      \
                  &Bthi[(size_t)(colBase + r1) * D + k0_ + c1 * 8], 16);           \
        cpasync16(sb_ + 3 * ARR_B + (r0 * SSTR + c0 * 8) * 2,                      \
                  &Btlo[(size_t)(colBase + r0) * D + k0_ + c0 * 8], 16);           \
        cpasync16(sb_ + 3 * ARR_B + (r1 * SSTR + c1 * 8) * 2,                      \
                  &Btlo[(size_t)(colBase + r1) * D + k0_ + c1 * 8], 16);           \
        cp_commit();                                                               \
    }

    PREFETCH(0, 0);

    for (int kc = 0; kc < D / BK; kc++) {
        const int s = kc & 1;
        if (kc + 1 < D / BK) {
            PREFETCH(kc + 1, s ^ 1);
            cp_wait1();
        } else {
            cp_wait0();
        }
        __syncthreads();

        const uint32_t sb = sbase + s * STG_B;
        const uint32_t aHiB = sb, aLoB = sb + ARR_B, bHiB = sb + 2 * ARR_B, bLoB = sb + 3 * ARR_B;

#pragma unroll
        for (int ks = 0; ks < 2; ks++) {
            const int kk = ks * 16;
            uint32_t ahi[2][4], alo[2][4];
#pragma unroll
            for (int mi = 0; mi < 2; mi++) {
                int row = wm * 32 + mi * 16 + (lane & 15);
                int col = kk + (lane >> 4) * 8;
                uint32_t off = (uint32_t)(row * SSTR + col) * 2;
                ldsm4(ahi[mi], aHiB + off);
                ldsm4(alo[mi], aLoB + off);
            }
            // B via x4: pair of n8 groups per load
            int brow = wn * 64 + (lane & 7) + ((lane >> 4) << 3);
            int bcol = kk + (((lane >> 3) & 1) << 3);
            uint32_t boff = (uint32_t)(brow * SSTR + bcol) * 2;
#pragma unroll
            for (int np = 0; np < 4; np++) {
                uint32_t bhi4[4], blo4[4];
                uint32_t off = boff + (uint32_t)(np * 16 * SSTR) * 2;
                ldsm4(bhi4, bHiB + off);
                ldsm4(blo4, bLoB + off);
#pragma unroll
                for (int mi = 0; mi < 2; mi++) {
                    mma16816(acc[mi][2 * np + 0], ahi[mi], bhi4 + 0);
                    mma16816(acc[mi][2 * np + 0], ahi[mi], blo4 + 0);
                    mma16816(acc[mi][2 * np + 0], alo[mi], bhi4 + 0);
                    mma16816(acc[mi][2 * np + 1], ahi[mi], bhi4 + 2);
                    mma16816(acc[mi][2 * np + 1], ahi[mi], blo4 + 2);
                    mma16816(acc[mi][2 * np + 1], alo[mi], bhi4 + 2);
                }
            }
        }
        __syncthreads();
    }
#undef PREFETCH

    // ---- epilogue: bias + relu
#pragma unroll
    for (int mi = 0; mi < 2; mi++) {
        int row0 = rowBase + wm * 32 + mi * 16 + (lane >> 2);
        int row1 = row0 + 8;
#pragma unroll
        for (int ni = 0; ni < 8; ni++) {
            int col = colBase + wn * 64 + ni * 8 + (lane & 3) * 2;
            float b0 = bias[col], b1 = bias[col + 1];
            float v00 = fmaxf(acc[mi][ni][0] + b0, 0.f);
            float v01 = fmaxf(acc[mi][ni][1] + b1, 0.f);
            float v10 = fmaxf(acc[mi][ni][2] + b0, 0.f);
            float v11 = fmaxf(acc[mi][ni][3] + b1, 0.f);
            if (mode == 0) {
                if (row0 < M) *(float2*)&Cf[(size_t)row0 * D + col] = make_float2(v00, v01);
                if (row1 < M) *(float2*)&Cf[(size_t)row1 * D + col] = make_float2(v10, v11);
            } else {
                __nv_bfloat16 h0 = __float2bfloat16(v00), h1 = __float2bfloat16(v01);
                __nv_bfloat16 h2 = __float2bfloat16(v10), h3 = __float2bfloat16(v11);
                __nv_bfloat16 l0 = __float2bfloat16(v00 - __bfloat162float(h0));
                __nv_bfloat16 l1 = __float2bfloat16(v01 - __bfloat162float(h1));
                __nv_bfloat16 l2 = __float2bfloat16(v10 - __bfloat162float(h2));
                __nv_bfloat16 l3 = __float2bfloat16(v11 - __bfloat162float(h3));
                if (row0 < M) {
                    *(uint32_t*)&Chi[(size_t)row0 * D + col] =
                        (uint32_t)__bfloat16_as_ushort(h0) | ((uint32_t)__bfloat16_as_ushort(h1) << 16);
                    *(uint32_t*)&Clo[(size_t)row0 * D + col] =
                        (uint32_t)__bfloat16_as_ushort(l0) | ((uint32_t)__bfloat16_as_ushort(l1) << 16);
                }
                if (row1 < M) {
                    *(uint32_t*)&Chi[(size_t)row1 * D + col] =
                        (uint32_t)__bfloat16_as_ushort(h2) | ((uint32_t)__bfloat16_as_ushort(h3) << 16);
                    *(uint32_t*)&Clo[(size_t)row1 * D + col] =
                        (uint32_t)__bfloat16_as_ushort(l2) | ((uint32_t)__bfloat16_as_ushort(l3) << 16);
                }
            }
        }
    }
}

// ---------------------------------------------------------------------------
// BatchNorm stats + final apply
// ---------------------------------------------------------------------------
__global__ void k_bnstats(const float* __restrict__ h) {
    const int ROWS_PER = 200;
    int r0 = blockIdx.x * ROWS_PER;
    int c1 = threadIdx.x;
    int c2 = threadIdx.x + 256;
    float s1 = 0.f, q1 = 0.f, s2 = 0.f, q2 = 0.f;
    int rend = min(r0 + ROWS_PER, N_NODES);
    for (int r = r0; r < rend; r++) {
        float a = h[r * D + c1];
        float b = h[r * D + c2];
        s1 += a; q1 += a * a;
        s2 += b; q2 += b * b;
    }
    atomicAdd(&g_bnsum[c1], s1); atomicAdd(&g_bnsq[c1], q1);
    atomicAdd(&g_bnsum[c2], s2); atomicAdd(&g_bnsq[c2], q2);
}

__global__ void k_bnapply(float* __restrict__ h,
                          const float* __restrict__ gamma, const float* __restrict__ beta) {
    int idx = blockIdx.x * blockDim.x + threadIdx.x;
    if (idx >= N_NODES * D) return;
    int c = idx & (D - 1);
    const float invN = 1.0f / N_NODES;
    float mean = g_bnsum[c] * invN;
    float var = g_bnsq[c] * invN - mean * mean;
    float sc = gamma[c] * rsqrtf(var + BN_EPS);
    h[idx] = (h[idx] - mean) * sc + beta[c];
}

// ---------------------------------------------------------------------------
// Pool + head
// ---------------------------------------------------------------------------
__global__ void k_poolscatter(const float* __restrict__ h, const int* __restrict__ batch) {
    int idx = blockIdx.x * blockDim.x + threadIdx.x;
    if (idx >= N_NODES * (D / 4)) return;
    int n = idx >> 7;
    int g = (idx & 127) << 2;
    int b = batch[n];
    float4 v = *(const float4*)&h[n * D + g];
    red_add_v4(&g_pool[b * D + g], v);
}
__global__ void k_count(const int* __restrict__ batch) {
    int n = blockIdx.x * blockDim.x + threadIdx.x;
    if (n < N_NODES) atomicAdd(&g_cnt[batch[n]], 1.0f);
}
__global__ void k_head(const float* __restrict__ Wfc, const float* __restrict__ bfc,
                       const float* __restrict__ Wlog, const float* __restrict__ blog,
                       float* __restrict__ out) {
    __shared__ float sp[D];
    __shared__ float sf[D];
    int g = blockIdx.x;
    int t = threadIdx.x;
    float invc = 1.0f / fmaxf(g_cnt[g], 1.0f);
    sp[t] = g_pool[g * D + t] * invc;
    __syncthreads();
    float f = bfc[t];
    for (int k = 0; k < D; k++) f += sp[k] * Wfc[k * D + t];
    sf[t] = tanhf(f);
    __syncthreads();
    if (t < N_OUT) {
        float l = blog[t];
        for (int k = 0; k < D; k++) l += sf[k] * Wlog[k * N_OUT + t];
        out[g * N_OUT + t] = l;
    }
}

// ---------------------------------------------------------------------------
// Launcher
// ---------------------------------------------------------------------------
extern "C" void kernel_launch(void* const* d_in, const int* in_sizes, int n_in,
                              void* d_out, int out_size) {
    const float* x     = (const float*)d_in[0];
    const int*   ei    = (const int*)d_in[1];
    const int*   batch = (const int*)d_in[2];
    const float* W1a   = (const float*)d_in[3];
    const float* b1a   = (const float*)d_in[4];
    const float* W1b   = (const float*)d_in[5];
    const float* b1b   = (const float*)d_in[6];
    const float* Wa    = (const float*)d_in[7];
    const float* ba    = (const float*)d_in[8];
    const float* Wb    = (const float*)d_in[9];
    const float* bb    = (const float*)d_in[10];
    const float* bn_g  = (const float*)d_in[11];
    const float* bn_b  = (const float*)d_in[12];
    const float* Wfc   = (const float*)d_in[13];
    const float* bfc   = (const float*)d_in[14];
    const float* Wlog  = (const float*)d_in[15];
    const float* blog  = (const float*)d_in[16];
    float* out = (float*)d_out;

    const int* src = ei;
    const int* dst = ei + N_EDGES;

    float *h, *agg16;
    __nv_bfloat16 *whi, *wlo, *thi, *tlo, *ahi, *alo;
    cudaGetSymbolAddress((void**)&h,     g_h);
    cudaGetSymbolAddress((void**)&agg16, g_agg16);
    cudaGetSymbolAddress((void**)&whi,   g_Whi);
    cudaGetSymbolAddress((void**)&wlo,   g_Wlo);
    cudaGetSymbolAddress((void**)&thi,   g_tHi);
    cudaGetSymbolAddress((void**)&tlo,   g_tLo);
    cudaGetSymbolAddress((void**)&ahi,   g_aHi);
    cudaGetSymbolAddress((void**)&alo,   g_aLo);

    cudaFuncSetAttribute(k_gemm512_mma, cudaFuncAttributeMaxDynamicSharedMemorySize, GEMM_SMEM);

    const int TB = 256;
    dim3 gemmGrid((N_NODES + BM - 1) / BM, D / BN);
    const size_t DD = (size_t)D * D;

    // CSR build + weight pre-convert (both independent of main flow)
    k_zero_deg<<<(N_NODES + TB - 1) / TB, TB>>>();
    k_deg<<<(N_EDGES + TB - 1) / TB, TB>>>(dst);
    k_scan<<<1, 1024>>>();
    k_fill<<<(N_EDGES + TB - 1) / TB, TB>>>(src, dst);
    k_convW<<<dim3(16, 16, 9), dim3(32, 8)>>>(W1b, Wa, Wb);

    // ---- layer 1 ----
    k_copy4<<<(N_NODES * IN_F / 4 + TB - 1) / TB, TB>>>(agg16, x, N_NODES * IN_F / 4);
    k_scatter16<<<(N_EDGES * 4 + TB - 1) / TB, TB>>>(x, src, dst);
    k_gemm16<<<(N_NODES * 128 + TB - 1) / TB, TB>>>(W1a, b1a);
    k_gemm512_mma<<<gemmGrid, TB, GEMM_SMEM>>>(thi, tlo, whi, wlo, b1b, h,
                                               ((__nv_bfloat16*)0), ((__nv_bfloat16*)0),
                                               N_NODES, 0);
    k_zero_bn<<<2, 256>>>();
    k_bnstats<<<50, 256>>>(h);

    // ---- layers 2..5 ----
    for (int i = 0; i < 4; i++) {
        // gather (with fused BN of previous layer) -> split bf16 A
        k_gather_bn<<<(N_NODES * 4 * 32 + TB - 1) / TB, TB>>>(h, bn_g + i * D, bn_b + i * D,
                                                              ahi, alo);
        k_gemm512_mma<<<gemmGrid, TB, GEMM_SMEM>>>(ahi, alo,
                                                   whi + (size_t)(1 + 2 * i) * DD,
                                                   wlo + (size_t)(1 + 2 * i) * DD,
                                                   ba + i * D, ((float*)0), thi, tlo,
                                                   N_NODES, 1);
        k_gemm512_mma<<<gemmGrid, TB, GEMM_SMEM>>>(thi, tlo,
                                                   whi + (size_t)(2 + 2 * i) * DD,
                                                   wlo + (size_t)(2 + 2 * i) * DD,
                                                   bb + i * D, h,
                                                   ((__nv_bfloat16*)0), ((__nv_bfloat16*)0),
                                                   N_NODES, 0);
        k_zero_bn<<<2, 256>>>();
        k_bnstats<<<50, 256>>>(h);
    }

    // final BN apply (layer-5 BN params), then pooling + head
    k_bnapply<<<(N_NODES * D + TB - 1) / TB, TB>>>(h, bn_g + 4 * D, bn_b + 4 * D);
    k_zero_pool<<<(N_GRAPHS * D + TB - 1) / TB, TB>>>();
    k_poolscatter<<<(N_NODES * 128 + TB - 1) / TB, TB>>>(h, batch);
    k_count<<<(N_NODES + TB - 1) / TB, TB>>>(batch);
    k_head<<<N_GRAPHS, D>>>(Wfc, bfc, Wlog, blog, out);
}

// round 7
// speedup vs baseline: 2.5833x; 1.1181x over previous
#include <cuda_runtime.h>
#include <cuda_bf16.h>
#include <stdint.h>
#include <math.h>

#define N_NODES 10000
#define N_EDGES 160000
#define IN_F    16
#define D       512
#define N_GRAPHS 64
#define N_OUT   18
#define BN_EPS  1e-5f

// ---------------------------------------------------------------------------
// Scratch
// ---------------------------------------------------------------------------
__device__ float g_h[N_NODES * D];
__device__ float g_agg16[N_NODES * IN_F];
__device__ __nv_bfloat16 g_tHi[N_NODES * D];
__device__ __nv_bfloat16 g_tLo[N_NODES * D];
__device__ __nv_bfloat16 g_aHi[N_NODES * D];
__device__ __nv_bfloat16 g_aLo[N_NODES * D];
__device__ float g_bnsum[D];
__device__ float g_bnsq[D];
__device__ float g_pool[N_GRAPHS * D];
__device__ float g_cnt[N_GRAPHS];
__device__ __nv_bfloat16 g_Whi[9 * D * D];
__device__ __nv_bfloat16 g_Wlo[9 * D * D];
// CSR
__device__ int g_deg[N_NODES];
__device__ int g_rowptr[N_NODES + 1];
__device__ int g_colidx[N_EDGES];

typedef unsigned long long ull;

__device__ __forceinline__ void red_add_v4(float* p, float4 v) {
    asm volatile("red.global.add.v4.f32 [%0], {%1,%2,%3,%4};"
                 :: "l"(p), "f"(v.x), "f"(v.y), "f"(v.z), "f"(v.w) : "memory");
}
__device__ __forceinline__ uint32_t smem_u32(const void* p) {
    uint32_t a;
    asm("{ .reg .u64 t; cvta.to.shared.u64 t, %1; cvt.u32.u64 %0, t; }" : "=r"(a) : "l"(p));
    return a;
}
__device__ __forceinline__ void ldsm4(uint32_t* r, uint32_t p) {
    asm volatile("ldmatrix.sync.aligned.m8n8.x4.shared.b16 {%0,%1,%2,%3}, [%4];"
                 : "=r"(r[0]), "=r"(r[1]), "=r"(r[2]), "=r"(r[3]) : "r"(p));
}
__device__ __forceinline__ void mma16816(float* d, const uint32_t* a, const uint32_t* b) {
    asm volatile(
        "mma.sync.aligned.m16n8k16.row.col.f32.bf16.bf16.f32 "
        "{%0,%1,%2,%3}, {%4,%5,%6,%7}, {%8,%9}, {%0,%1,%2,%3};"
        : "+f"(d[0]), "+f"(d[1]), "+f"(d[2]), "+f"(d[3])
        : "r"(a[0]), "r"(a[1]), "r"(a[2]), "r"(a[3]), "r"(b[0]), "r"(b[1]));
}
__device__ __forceinline__ void cpasync16(uint32_t dst, const void* src, int validsz) {
    asm volatile("cp.async.ca.shared.global [%0], [%1], 16, %2;"
                 :: "r"(dst), "l"(src), "r"(validsz));
}
__device__ __forceinline__ void cp_commit() { asm volatile("cp.async.commit_group;" ::: "memory"); }
__device__ __forceinline__ void cp_wait1()  { asm volatile("cp.async.wait_group 1;" ::: "memory"); }
__device__ __forceinline__ void cp_wait0()  { asm volatile("cp.async.wait_group 0;" ::: "memory"); }

__device__ __forceinline__ ull split_pack4(float4 v, ull& plo) {
    __nv_bfloat16 h0 = __float2bfloat16(v.x), h1 = __float2bfloat16(v.y);
    __nv_bfloat16 h2 = __float2bfloat16(v.z), h3 = __float2bfloat16(v.w);
    __nv_bfloat16 l0 = __float2bfloat16(v.x - __bfloat162float(h0));
    __nv_bfloat16 l1 = __float2bfloat16(v.y - __bfloat162float(h1));
    __nv_bfloat16 l2 = __float2bfloat16(v.z - __bfloat162float(h2));
    __nv_bfloat16 l3 = __float2bfloat16(v.w - __bfloat162float(h3));
    plo = (ull)__bfloat16_as_ushort(l0) | ((ull)__bfloat16_as_ushort(l1) << 16)
        | ((ull)__bfloat16_as_ushort(l2) << 32) | ((ull)__bfloat16_as_ushort(l3) << 48);
    return (ull)__bfloat16_as_ushort(h0) | ((ull)__bfloat16_as_ushort(h1) << 16)
         | ((ull)__bfloat16_as_ushort(h2) << 32) | ((ull)__bfloat16_as_ushort(h3) << 48);
}

// ---------------------------------------------------------------------------
// Utility kernels
// ---------------------------------------------------------------------------
__global__ void k_copy4(float* __restrict__ dst, const float* __restrict__ src, int n4) {
    int i = blockIdx.x * blockDim.x + threadIdx.x;
    if (i < n4) ((float4*)dst)[i] = ((const float4*)src)[i];
}
__global__ void k_zero_bn() {
    int i = blockIdx.x * blockDim.x + threadIdx.x;
    if (i < D) { g_bnsum[i] = 0.f; g_bnsq[i] = 0.f; }
}
__global__ void k_zero_pool() {
    int i = blockIdx.x * blockDim.x + threadIdx.x;
    if (i < N_GRAPHS * D) g_pool[i] = 0.f;
    if (i < N_GRAPHS) g_cnt[i] = 0.f;
}

// ---------------------------------------------------------------------------
// CSR build
// ---------------------------------------------------------------------------
__global__ void k_zero_deg() {
    int i = blockIdx.x * blockDim.x + threadIdx.x;
    if (i < N_NODES) g_deg[i] = 0;
}
__global__ void k_deg(const int* __restrict__ dst) {
    int e = blockIdx.x * blockDim.x + threadIdx.x;
    if (e < N_EDGES) atomicAdd(&g_deg[dst[e]], 1);
}
__global__ void k_scan() {
    __shared__ int ssum[1024];
    int t = threadIdx.x;
    int base = t * 10;
    int loc[10];
    int s = 0;
#pragma unroll
    for (int i = 0; i < 10; i++) {
        int idx = base + i;
        int v = (idx < N_NODES) ? g_deg[idx] : 0;
        loc[i] = s; s += v;
    }
    ssum[t] = s;
    __syncthreads();
    for (int off = 1; off < 1024; off <<= 1) {
        int add = (t >= off) ? ssum[t - off] : 0;
        __syncthreads();
        ssum[t] += add;
        __syncthreads();
    }
    int excl = ssum[t] - s;
#pragma unroll
    for (int i = 0; i < 10; i++) {
        int idx = base + i;
        if (idx < N_NODES) { g_rowptr[idx] = excl + loc[i]; g_deg[idx] = 0; }
    }
    if (t == 0) g_rowptr[N_NODES] = N_EDGES;
}
__global__ void k_fill(const int* __restrict__ src, const int* __restrict__ dst) {
    int e = blockIdx.x * blockDim.x + threadIdx.x;
    if (e >= N_EDGES) return;
    int d = dst[e];
    int p = atomicAdd(&g_deg[d], 1);
    g_colidx[g_rowptr[d] + p] = src[e];
}

// ---------------------------------------------------------------------------
// Weight convert + transpose: out[m][n][k] = split(W_m[k][n])
// ---------------------------------------------------------------------------
__global__ void k_convW(const float* __restrict__ W1b, const float* __restrict__ Wa,
                        const float* __restrict__ Wb) {
    __shared__ float tile[32][33];
    int m = blockIdx.z;
    const float* W = (m == 0) ? W1b
                   : ((m & 1) ? Wa + (size_t)((m - 1) >> 1) * D * D
                              : Wb + (size_t)((m - 2) >> 1) * D * D);
    int tx = threadIdx.x, ty = threadIdx.y;
    int n0 = blockIdx.x * 32, k0 = blockIdx.y * 32;
#pragma unroll
    for (int j = 0; j < 32; j += 8)
        tile[ty + j][tx] = W[(k0 + ty + j) * D + n0 + tx];
    __syncthreads();
#pragma unroll
    for (int j = 0; j < 32; j += 8) {
        float v = tile[tx][ty + j];
        int n = n0 + ty + j, k = k0 + tx;
        __nv_bfloat16 hi = __float2bfloat16(v);
        __nv_bfloat16 lo = __float2bfloat16(v - __bfloat162float(hi));
        size_t o = (size_t)m * D * D + (size_t)n * D + k;
        g_Whi[o] = hi;
        g_Wlo[o] = lo;
    }
}

// ---------------------------------------------------------------------------
// Layer-1 aggregation + small GEMM (IN_F=16), emits split bf16 + relu
// ---------------------------------------------------------------------------
__global__ void k_scatter16(const float* __restrict__ x,
                            const int* __restrict__ src, const int* __restrict__ dst) {
    int idx = blockIdx.x * blockDim.x + threadIdx.x;
    if (idx >= N_EDGES * 4) return;
    int e = idx >> 2;
    int g = (idx & 3) << 2;
    int s = src[e], d = dst[e];
    float4 v = *(const float4*)&x[s * IN_F + g];
    red_add_v4(&g_agg16[d * IN_F + g], v);
}

__global__ void k_gemm16(const float* __restrict__ W, const float* __restrict__ bias) {
    int idx = blockIdx.x * blockDim.x + threadIdx.x;
    if (idx >= N_NODES * (D / 4)) return;
    int n = idx >> 7;
    int c = (idx & 127) << 2;
    float4 acc = *(const float4*)&bias[c];
    const float* arow = &g_agg16[n * IN_F];
#pragma unroll
    for (int k = 0; k < IN_F; k++) {
        float a = arow[k];
        float4 w = *(const float4*)&W[k * D + c];
        acc.x += a * w.x; acc.y += a * w.y; acc.z += a * w.z; acc.w += a * w.w;
    }
    acc.x = fmaxf(acc.x, 0.f); acc.y = fmaxf(acc.y, 0.f);
    acc.z = fmaxf(acc.z, 0.f); acc.w = fmaxf(acc.w, 0.f);
    ull pl;
    ull ph = split_pack4(acc, pl);
    *(ull*)&g_tHi[n * D + c] = ph;
    *(ull*)&g_tLo[n * D + c] = pl;
}

// ---------------------------------------------------------------------------
// CSR gather + fused BN-apply + hi/lo split.
// ---------------------------------------------------------------------------
__global__ __launch_bounds__(256)
void k_gather_bn(const float* __restrict__ h,
                 const float* __restrict__ gamma, const float* __restrict__ beta,
                 __nv_bfloat16* __restrict__ Hi, __nv_bfloat16* __restrict__ Lo) {
    int gw = (blockIdx.x * 256 + threadIdx.x) >> 5;
    if (gw >= N_NODES * 4) return;
    int lane = threadIdx.x & 31;
    int n = gw >> 2;
    int c = ((gw & 3) << 7) + lane * 4;

    float4 acc = *(const float4*)&h[(size_t)n * D + c];
    int e0 = g_rowptr[n], e1 = g_rowptr[n + 1];
    int e = e0;
    for (; e + 2 <= e1; e += 2) {
        int s0 = g_colidx[e], s1 = g_colidx[e + 1];
        float4 v0 = *(const float4*)&h[(size_t)s0 * D + c];
        float4 v1 = *(const float4*)&h[(size_t)s1 * D + c];
        acc.x += v0.x + v1.x; acc.y += v0.y + v1.y;
        acc.z += v0.z + v1.z; acc.w += v0.w + v1.w;
    }
    if (e < e1) {
        int s0 = g_colidx[e];
        float4 v0 = *(const float4*)&h[(size_t)s0 * D + c];
        acc.x += v0.x; acc.y += v0.y; acc.z += v0.z; acc.w += v0.w;
    }
    float cnt = (float)(e1 - e0 + 1);
    const float invN = 1.0f / N_NODES;
    float4 bs = *(const float4*)&g_bnsum[c];
    float4 bq = *(const float4*)&g_bnsq[c];
    float4 gm = *(const float4*)&gamma[c];
    float4 bt = *(const float4*)&beta[c];
    float m0 = bs.x * invN, m1 = bs.y * invN, m2 = bs.z * invN, m3 = bs.w * invN;
    float s0 = gm.x * rsqrtf(bq.x * invN - m0 * m0 + BN_EPS);
    float s1 = gm.y * rsqrtf(bq.y * invN - m1 * m1 + BN_EPS);
    float s2 = gm.z * rsqrtf(bq.z * invN - m2 * m2 + BN_EPS);
    float s3 = gm.w * rsqrtf(bq.w * invN - m3 * m3 + BN_EPS);
    float4 o;
    o.x = s0 * acc.x + cnt * (bt.x - s0 * m0);
    o.y = s1 * acc.y + cnt * (bt.y - s1 * m1);
    o.z = s2 * acc.z + cnt * (bt.z - s2 * m2);
    o.w = s3 * acc.w + cnt * (bt.w - s3 * m3);
    ull pl;
    ull ph = split_pack4(o, pl);
    *(ull*)&Hi[(size_t)n * D + c] = ph;
    *(ull*)&Lo[(size_t)n * D + c] = pl;
}

// ---------------------------------------------------------------------------
// HMMA GEMM, all-bf16 inputs, cp.async double-buffered.
// mode 0: out f32 + relu + fused BN-stats accumulation into g_bnsum/g_bnsq.
// mode 1: out split bf16 + relu.
// ---------------------------------------------------------------------------
#define BM 128
#define BN 128
#define BK 32
#define SSTR 40
#define ARR_B (128 * SSTR * 2)
#define STG_B (4 * ARR_B)
#define GEMM_SMEM (2 * STG_B)

__global__ __launch_bounds__(256, 2)
void k_gemm512_mma(const __nv_bfloat16* __restrict__ Ahi,
                   const __nv_bfloat16* __restrict__ Alo,
                   const __nv_bfloat16* __restrict__ Bthi,
                   const __nv_bfloat16* __restrict__ Btlo,
                   const float* __restrict__ bias,
                   float* __restrict__ Cf,
                   __nv_bfloat16* __restrict__ Chi,
                   __nv_bfloat16* __restrict__ Clo,
                   int M, int mode) {
    extern __shared__ char sm[];
    const uint32_t sbase = smem_u32(sm);

    const int tid = threadIdx.x;
    const int lane = tid & 31;
    const int warp = tid >> 5;
    const int wm = warp & 3;
    const int wn = warp >> 2;
    const int rowBase = blockIdx.x * BM;
    const int colBase = blockIdx.y * BN;

    const int r0 = tid >> 2,         c0 = tid & 3;
    const int r1 = (tid + 256) >> 2, c1 = tid & 3;
    const int av0 = (rowBase + r0 < M) ? 16 : 0;
    const int av1 = (rowBase + r1 < M) ? 16 : 0;

    float acc[2][8][4];
#pragma unroll
    for (int mi = 0; mi < 2; mi++)
#pragma unroll
        for (int ni = 0; ni < 8; ni++)
#pragma unroll
            for (int j = 0; j < 4; j++) acc[mi][ni][j] = 0.f;

#define PREFETCH(kc_, s_)                                                          \
    {                                                                              \
        const int k0_ = (kc_) * BK;                                                \
        const uint32_t sb_ = sbase + (s_) * STG_B;                                 \
        cpasync16(sb_ + 0 * ARR_B + (r0 * SSTR + c0 * 8) * 2,                      \
                  &Ahi[(size_t)(rowBase + r0) * D + k0_ + c0 * 8], av0);           \
        cpasync16(sb_ + 0 * ARR_B + (r1 * SSTR + c1 * 8) * 2,                      \
                  &Ahi[(size_t)(rowBase + r1) * D + k0_ + c1 * 8], av1);           \
        cpasync16(sb_ + 1 * ARR_B + (r0 * SSTR + c0 * 8) * 2,                      \
                  &Alo[(size_t)(rowBase + r0) * D + k0_ + c0 * 8], av0);           \
        cpasync16(sb_ + 1 * ARR_B + (r1 * SSTR + c1 * 8) * 2,                      \
                  &Alo[(size_t)(rowBase + r1) * D + k0_ + c1 * 8], av1);           \
        cpasync16(sb_ + 2 * ARR_B + (r0 * SSTR + c0 * 8) * 2,                      \
                  &Bthi[(size_t)(colBase + r0) * D + k0_ + c0 * 8], 16);           \
        cpasync16(sb_ + 2 * ARR_B + (r1 * SSTR + c1 * 8) * 2,                      \
                  &Bthi[(size_t)(colBase + r1) * D + k0_ + c1 * 8], 16);           \
        cpasync16(sb_ + 3 * ARR_B + (r0 * SSTR + c0 * 8) * 2,                      \
                  &Btlo[(size_t)(colBase + r0) * D + k0_ + c0 * 8], 16);           \
        cpasync16(sb_ + 3 * ARR_B + (r1 * SSTR + c1 * 8) * 2,                      \
                  &Btlo[(size_t)(colBase + r1) * D + k0_ + c1 * 8], 16);           \
        cp_commit();                                                               \
    }

    PREFETCH(0, 0);

    for (int kc = 0; kc < D / BK; kc++) {
        const int s = kc & 1;
        if (kc + 1 < D / BK) {
            PREFETCH(kc + 1, s ^ 1);
            cp_wait1();
        } else {
            cp_wait0();
        }
        __syncthreads();

        const uint32_t sb = sbase + s * STG_B;
        const uint32_t aHiB = sb, aLoB = sb + ARR_B, bHiB = sb + 2 * ARR_B, bLoB = sb + 3 * ARR_B;

#pragma unroll
        for (int ks = 0; ks < 2; ks++) {
            const int kk = ks * 16;
            uint32_t ahi[2][4], alo[2][4];
#pragma unroll
            for (int mi = 0; mi < 2; mi++) {
                int row = wm * 32 + mi * 16 + (lane & 15);
                int col = kk + (lane >> 4) * 8;
                uint32_t off = (uint32_t)(row * SSTR + col) * 2;
                ldsm4(ahi[mi], aHiB + off);
                ldsm4(alo[mi], aLoB + off);
            }
            int brow = wn * 64 + (lane & 7) + ((lane >> 4) << 3);
            int bcol = kk + (((lane >> 3) & 1) << 3);
            uint32_t boff = (uint32_t)(brow * SSTR + bcol) * 2;
#pragma unroll
            for (int np = 0; np < 4; np++) {
                uint32_t bhi4[4], blo4[4];
                uint32_t off = boff + (uint32_t)(np * 16 * SSTR) * 2;
                ldsm4(bhi4, bHiB + off);
                ldsm4(blo4, bLoB + off);
#pragma unroll
                for (int mi = 0; mi < 2; mi++) {
                    mma16816(acc[mi][2 * np + 0], ahi[mi], bhi4 + 0);
                    mma16816(acc[mi][2 * np + 0], ahi[mi], blo4 + 0);
                    mma16816(acc[mi][2 * np + 0], alo[mi], bhi4 + 0);
                    mma16816(acc[mi][2 * np + 1], ahi[mi], bhi4 + 2);
                    mma16816(acc[mi][2 * np + 1], ahi[mi], blo4 + 2);
                    mma16816(acc[mi][2 * np + 1], alo[mi], bhi4 + 2);
                }
            }
        }
        __syncthreads();
    }
#undef PREFETCH

    // ---- epilogue
    if (mode == 0) {
        // bias + relu + store f32 + fused BN stats
        float* scol = (float*)sm;          // 128 floats
        float* qcol = scol + 128;          // 128 floats
        if (tid < 128) { scol[tid] = 0.f; qcol[tid] = 0.f; }
        __syncthreads();
#pragma unroll
        for (int ni = 0; ni < 8; ni++) {
            int col = colBase + wn * 64 + ni * 8 + (lane & 3) * 2;
            float b0 = bias[col], b1 = bias[col + 1];
            float s0 = 0.f, q0 = 0.f, s1 = 0.f, q1 = 0.f;
#pragma unroll
            for (int mi = 0; mi < 2; mi++) {
                int row0 = rowBase + wm * 32 + mi * 16 + (lane >> 2);
                int row1 = row0 + 8;
                float v00 = fmaxf(acc[mi][ni][0] + b0, 0.f);
                float v01 = fmaxf(acc[mi][ni][1] + b1, 0.f);
                float v10 = fmaxf(acc[mi][ni][2] + b0, 0.f);
                float v11 = fmaxf(acc[mi][ni][3] + b1, 0.f);
                if (row0 < M) {
                    *(float2*)&Cf[(size_t)row0 * D + col] = make_float2(v00, v01);
                    s0 += v00; q0 += v00 * v00; s1 += v01; q1 += v01 * v01;
                }
                if (row1 < M) {
                    *(float2*)&Cf[(size_t)row1 * D + col] = make_float2(v10, v11);
                    s0 += v10; q0 += v10 * v10; s1 += v11; q1 += v11 * v11;
                }
            }
#pragma unroll
            for (int o = 4; o < 32; o <<= 1) {
                s0 += __shfl_xor_sync(0xffffffffu, s0, o);
                q0 += __shfl_xor_sync(0xffffffffu, q0, o);
                s1 += __shfl_xor_sync(0xffffffffu, s1, o);
                q1 += __shfl_xor_sync(0xffffffffu, q1, o);
            }
            if (lane < 4) {
                int lc = wn * 64 + ni * 8 + lane * 2;
                atomicAdd(&scol[lc], s0);
                atomicAdd(&qcol[lc], q0);
                atomicAdd(&scol[lc + 1], s1);
                atomicAdd(&qcol[lc + 1], q1);
            }
        }
        __syncthreads();
        if (tid < 128) {
            atomicAdd(&g_bnsum[colBase + tid], scol[tid]);
            atomicAdd(&g_bnsq[colBase + tid], qcol[tid]);
        }
    } else {
        // bias + relu + split bf16 store
#pragma unroll
        for (int mi = 0; mi < 2; mi++) {
            int row0 = rowBase + wm * 32 + mi * 16 + (lane >> 2);
            int row1 = row0 + 8;
#pragma unroll
            for (int ni = 0; ni < 8; ni++) {
                int col = colBase + wn * 64 + ni * 8 + (lane & 3) * 2;
                float b0 = bias[col], b1 = bias[col + 1];
                float v00 = fmaxf(acc[mi][ni][0] + b0, 0.f);
                float v01 = fmaxf(acc[mi][ni][1] + b1, 0.f);
                float v10 = fmaxf(acc[mi][ni][2] + b0, 0.f);
                float v11 = fmaxf(acc[mi][ni][3] + b1, 0.f);
                __nv_bfloat16 h0 = __float2bfloat16(v00), h1 = __float2bfloat16(v01);
                __nv_bfloat16 h2 = __float2bfloat16(v10), h3 = __float2bfloat16(v11);
                __nv_bfloat16 l0 = __float2bfloat16(v00 - __bfloat162float(h0));
                __nv_bfloat16 l1 = __float2bfloat16(v01 - __bfloat162float(h1));
                __nv_bfloat16 l2 = __float2bfloat16(v10 - __bfloat162float(h2));
                __nv_bfloat16 l3 = __float2bfloat16(v11 - __bfloat162float(h3));
                if (row0 < M) {
                    *(uint32_t*)&Chi[(size_t)row0 * D + col] =
                        (uint32_t)__bfloat16_as_ushort(h0) | ((uint32_t)__bfloat16_as_ushort(h1) << 16);
                    *(uint32_t*)&Clo[(size_t)row0 * D + col] =
                        (uint32_t)__bfloat16_as_ushort(l0) | ((uint32_t)__bfloat16_as_ushort(l1) << 16);
                }
                if (row1 < M) {
                    *(uint32_t*)&Chi[(size_t)row1 * D + col] =
                        (uint32_t)__bfloat16_as_ushort(h2) | ((uint32_t)__bfloat16_as_ushort(h3) << 16);
                    *(uint32_t*)&Clo[(size_t)row1 * D + col] =
                        (uint32_t)__bfloat16_as_ushort(l2) | ((uint32_t)__bfloat16_as_ushort(l3) << 16);
                }
            }
        }
    }
}

// ---------------------------------------------------------------------------
// Pool + head (BN affine applied to pooled means inside k_head)
// ---------------------------------------------------------------------------
__global__ void k_poolscatter(const float* __restrict__ h, const int* __restrict__ batch) {
    int idx = blockIdx.x * blockDim.x + threadIdx.x;
    if (idx >= N_NODES * (D / 4)) return;
    int n = idx >> 7;
    int g = (idx & 127) << 2;
    int b = batch[n];
    float4 v = *(const float4*)&h[n * D + g];
    red_add_v4(&g_pool[b * D + g], v);
}
__global__ void k_count(const int* __restrict__ batch) {
    int n = blockIdx.x * blockDim.x + threadIdx.x;
    if (n < N_NODES) atomicAdd(&g_cnt[batch[n]], 1.0f);
}
__global__ void k_head(const float* __restrict__ Wfc, const float* __restrict__ bfc,
                       const float* __restrict__ Wlog, const float* __restrict__ blog,
                       const float* __restrict__ gamma, const float* __restrict__ beta,
                       float* __restrict__ out) {
    __shared__ float sp[D];
    __shared__ float sf[D];
    int g = blockIdx.x;
    int t = threadIdx.x;
    float cnt = g_cnt[g];
    float invc = 1.0f / fmaxf(cnt, 1.0f);
    const float invN = 1.0f / N_NODES;
    float mean = g_bnsum[t] * invN;
    float var = g_bnsq[t] * invN - mean * mean;
    float sc = gamma[t] * rsqrtf(var + BN_EPS);
    // mean of normalized h over graph = sc*raw_mean + (beta - sc*mu); 0 if empty
    sp[t] = sc * (g_pool[g * D + t] * invc) + (cnt * invc) * (beta[t] - sc * mean);
    __syncthreads();
    float f = bfc[t];
    for (int k = 0; k < D; k++) f += sp[k] * Wfc[k * D + t];
    sf[t] = tanhf(f);
    __syncthreads();
    if (t < N_OUT) {
        float l = blog[t];
        for (int k = 0; k < D; k++) l += sf[k] * Wlog[k * N_OUT + t];
        out[g * N_OUT + t] = l;
    }
}

// ---------------------------------------------------------------------------
// Launcher
// ---------------------------------------------------------------------------
extern "C" void kernel_launch(void* const* d_in, const int* in_sizes, int n_in,
                              void* d_out, int out_size) {
    const float* x     = (const float*)d_in[0];
    const int*   ei    = (const int*)d_in[1];
    const int*   batch = (const int*)d_in[2];
    const float* W1a   = (const float*)d_in[3];
    const float* b1a   = (const float*)d_in[4];
    const float* W1b   = (const float*)d_in[5];
    const float* b1b   = (const float*)d_in[6];
    const float* Wa    = (const float*)d_in[7];
    const float* ba    = (const float*)d_in[8];
    const float* Wb    = (const float*)d_in[9];
    const float* bb    = (const float*)d_in[10];
    const float* bn_g  = (const float*)d_in[11];
    const float* bn_b  = (const float*)d_in[12];
    const float* Wfc   = (const float*)d_in[13];
    const float* bfc   = (const float*)d_in[14];
    const float* Wlog  = (const float*)d_in[15];
    const float* blog  = (const float*)d_in[16];
    float* out = (float*)d_out;

    const int* src = ei;
    const int* dst = ei + N_EDGES;

    float *h, *agg16;
    __nv_bfloat16 *whi, *wlo, *thi, *tlo, *ahi, *alo;
    cudaGetSymbolAddress((void**)&h,     g_h);
    cudaGetSymbolAddress((void**)&agg16, g_agg16);
    cudaGetSymbolAddress((void**)&whi,   g_Whi);
    cudaGetSymbolAddress((void**)&wlo,   g_Wlo);
    cudaGetSymbolAddress((void**)&thi,   g_tHi);
    cudaGetSymbolAddress((void**)&tlo,   g_tLo);
    cudaGetSymbolAddress((void**)&ahi,   g_aHi);
    cudaGetSymbolAddress((void**)&alo,   g_aLo);

    cudaFuncSetAttribute(k_gemm512_mma, cudaFuncAttributeMaxDynamicSharedMemorySize, GEMM_SMEM);

    const int TB = 256;
    dim3 gemmGrid((N_NODES + BM - 1) / BM, D / BN);
    const size_t DD = (size_t)D * D;

    // CSR build + weight pre-convert
    k_zero_deg<<<(N_NODES + TB - 1) / TB, TB>>>();
    k_deg<<<(N_EDGES + TB - 1) / TB, TB>>>(dst);
    k_scan<<<1, 1024>>>();
    k_fill<<<(N_EDGES + TB - 1) / TB, TB>>>(src, dst);
    k_convW<<<dim3(16, 16, 9), dim3(32, 8)>>>(W1b, Wa, Wb);

    // ---- layer 1 ----
    k_copy4<<<(N_NODES * IN_F / 4 + TB - 1) / TB, TB>>>(agg16, x, N_NODES * IN_F / 4);
    k_scatter16<<<(N_EDGES * 4 + TB - 1) / TB, TB>>>(x, src, dst);
    k_gemm16<<<(N_NODES * 128 + TB - 1) / TB, TB>>>(W1a, b1a);
    k_zero_bn<<<2, 256>>>();
    k_gemm512_mma<<<gemmGrid, TB, GEMM_SMEM>>>(thi, tlo, whi, wlo, b1b, h,
                                               ((__nv_bfloat16*)0), ((__nv_bfloat16*)0),
                                               N_NODES, 0);

    // ---- layers 2..5 ----
    for (int i = 0; i < 4; i++) {
        k_gather_bn<<<(N_NODES * 4 * 32 + TB - 1) / TB, TB>>>(h, bn_g + i * D, bn_b + i * D,
                                                              ahi, alo);
        k_gemm512_mma<<<gemmGrid, TB, GEMM_SMEM>>>(ahi, alo,
                                                   whi + (size_t)(1 + 2 * i) * DD,
                                                   wlo + (size_t)(1 + 2 * i) * DD,
                                                   ba + i * D, ((float*)0), thi, tlo,
                                                   N_NODES, 1);
        k_zero_bn<<<2, 256>>>();
        k_gemm512_mma<<<gemmGrid, TB, GEMM_SMEM>>>(thi, tlo,
                                                   whi + (size_t)(2 + 2 * i) * DD,
                                                   wlo + (size_t)(2 + 2 * i) * DD,
                                                   bb + i * D, h,
                                                   ((__nv_bfloat16*)0), ((__nv_bfloat16*)0),
                                                   N_NODES, 0);
    }

    // ---- pooling + head (BN5 applied on pooled means) ----
    k_zero_pool<<<(N_GRAPHS * D + TB - 1) / TB, TB>>>();
    k_poolscatter<<<(N_NODES * 128 + TB - 1) / TB, TB>>>(h, batch);
    k_count<<<(N_NODES + TB - 1) / TB, TB>>>(batch);
    k_head<<<N_GRAPHS, D>>>(Wfc, bfc, Wlog, blog, bn_g + 4 * D, bn_b + 4 * D, out);
}

// round 8
// speedup vs baseline: 2.8306x; 1.0957x over previous
#include <cuda_runtime.h>
#include <cuda_bf16.h>
#include <stdint.h>
#include <math.h>

#define N_NODES 10000
#define N_EDGES 160000
#define IN_F    16
#define D       512
#define N_GRAPHS 64
#define N_OUT   18
#define BN_EPS  1e-5f

// ---------------------------------------------------------------------------
// Scratch
// ---------------------------------------------------------------------------
__device__ float g_h[N_NODES * D];
__device__ float g_agg16[N_NODES * IN_F];
__device__ __nv_bfloat16 g_tHi[N_NODES * D];
__device__ __nv_bfloat16 g_tLo[N_NODES * D];
__device__ __nv_bfloat16 g_aHi[N_NODES * D];
__device__ __nv_bfloat16 g_aLo[N_NODES * D];
__device__ float g_bnsum[D];
__device__ float g_bnsq[D];
__device__ float g_pool[N_GRAPHS * D];
__device__ float g_cnt[N_GRAPHS];
__device__ __nv_bfloat16 g_Whi[9 * D * D];
__device__ __nv_bfloat16 g_Wlo[9 * D * D];
// CSR
__device__ int g_deg[N_NODES];
__device__ int g_rowptr[N_NODES + 1];
__device__ int g_colidx[N_EDGES];

typedef unsigned long long ull;

__device__ __forceinline__ void red_add_v4(float* p, float4 v) {
    asm volatile("red.global.add.v4.f32 [%0], {%1,%2,%3,%4};"
                 :: "l"(p), "f"(v.x), "f"(v.y), "f"(v.z), "f"(v.w) : "memory");
}
__device__ __forceinline__ uint32_t smem_u32(const void* p) {
    uint32_t a;
    asm("{ .reg .u64 t; cvta.to.shared.u64 t, %1; cvt.u32.u64 %0, t; }" : "=r"(a) : "l"(p));
    return a;
}
__device__ __forceinline__ void ldsm4(uint32_t* r, uint32_t p) {
    asm volatile("ldmatrix.sync.aligned.m8n8.x4.shared.b16 {%0,%1,%2,%3}, [%4];"
                 : "=r"(r[0]), "=r"(r[1]), "=r"(r[2]), "=r"(r[3]) : "r"(p));
}
__device__ __forceinline__ void mma16816(float* d, const uint32_t* a, const uint32_t* b) {
    asm volatile(
        "mma.sync.aligned.m16n8k16.row.col.f32.bf16.bf16.f32 "
        "{%0,%1,%2,%3}, {%4,%5,%6,%7}, {%8,%9}, {%0,%1,%2,%3};"
        : "+f"(d[0]), "+f"(d[1]), "+f"(d[2]), "+f"(d[3])
        : "r"(a[0]), "r"(a[1]), "r"(a[2]), "r"(a[3]), "r"(b[0]), "r"(b[1]));
}
__device__ __forceinline__ void cpasync16(uint32_t dst, const void* src, int validsz) {
    asm volatile("cp.async.ca.shared.global [%0], [%1], 16, %2;"
                 :: "r"(dst), "l"(src), "r"(validsz));
}
__device__ __forceinline__ void cp_commit() { asm volatile("cp.async.commit_group;" ::: "memory"); }
__device__ __forceinline__ void cp_wait1()  { asm volatile("cp.async.wait_group 1;" ::: "memory"); }
__device__ __forceinline__ void cp_wait0()  { asm volatile("cp.async.wait_group 0;" ::: "memory"); }

// SW64 swizzle: XOR byte bits[4:5] with bits[7:8] (row pair index).
__device__ __forceinline__ uint32_t swz(uint32_t b) { return b ^ ((b >> 3) & 0x30); }

__device__ __forceinline__ ull split_pack4(float4 v, ull& plo) {
    __nv_bfloat16 h0 = __float2bfloat16(v.x), h1 = __float2bfloat16(v.y);
    __nv_bfloat16 h2 = __float2bfloat16(v.z), h3 = __float2bfloat16(v.w);
    __nv_bfloat16 l0 = __float2bfloat16(v.x - __bfloat162float(h0));
    __nv_bfloat16 l1 = __float2bfloat16(v.y - __bfloat162float(h1));
    __nv_bfloat16 l2 = __float2bfloat16(v.z - __bfloat162float(h2));
    __nv_bfloat16 l3 = __float2bfloat16(v.w - __bfloat162float(h3));
    plo = (ull)__bfloat16_as_ushort(l0) | ((ull)__bfloat16_as_ushort(l1) << 16)
        | ((ull)__bfloat16_as_ushort(l2) << 32) | ((ull)__bfloat16_as_ushort(l3) << 48);
    return (ull)__bfloat16_as_ushort(h0) | ((ull)__bfloat16_as_ushort(h1) << 16)
         | ((ull)__bfloat16_as_ushort(h2) << 32) | ((ull)__bfloat16_as_ushort(h3) << 48);
}

// ---------------------------------------------------------------------------
// Utility kernels
// ---------------------------------------------------------------------------
__global__ void k_copy4(float* __restrict__ dst, const float* __restrict__ src, int n4) {
    int i = blockIdx.x * blockDim.x + threadIdx.x;
    if (i < n4) ((float4*)dst)[i] = ((const float4*)src)[i];
}
__global__ void k_zero_bn() {
    int i = blockIdx.x * blockDim.x + threadIdx.x;
    if (i < D) { g_bnsum[i] = 0.f; g_bnsq[i] = 0.f; }
}
__global__ void k_zero_pool() {
    int i = blockIdx.x * blockDim.x + threadIdx.x;
    if (i < N_GRAPHS * D) g_pool[i] = 0.f;
    if (i < N_GRAPHS) g_cnt[i] = 0.f;
}

// ---------------------------------------------------------------------------
// CSR build
// ---------------------------------------------------------------------------
__global__ void k_zero_deg() {
    int i = blockIdx.x * blockDim.x + threadIdx.x;
    if (i < N_NODES) g_deg[i] = 0;
}
__global__ void k_deg(const int* __restrict__ dst) {
    int e = blockIdx.x * blockDim.x + threadIdx.x;
    if (e < N_EDGES) atomicAdd(&g_deg[dst[e]], 1);
}
__global__ void k_scan() {
    __shared__ int ssum[1024];
    int t = threadIdx.x;
    int base = t * 10;
    int loc[10];
    int s = 0;
#pragma unroll
    for (int i = 0; i < 10; i++) {
        int idx = base + i;
        int v = (idx < N_NODES) ? g_deg[idx] : 0;
        loc[i] = s; s += v;
    }
    ssum[t] = s;
    __syncthreads();
    for (int off = 1; off < 1024; off <<= 1) {
        int add = (t >= off) ? ssum[t - off] : 0;
        __syncthreads();
        ssum[t] += add;
        __syncthreads();
    }
    int excl = ssum[t] - s;
#pragma unroll
    for (int i = 0; i < 10; i++) {
        int idx = base + i;
        if (idx < N_NODES) { g_rowptr[idx] = excl + loc[i]; g_deg[idx] = 0; }
    }
    if (t == 0) g_rowptr[N_NODES] = N_EDGES;
}
__global__ void k_fill(const int* __restrict__ src, const int* __restrict__ dst) {
    int e = blockIdx.x * blockDim.x + threadIdx.x;
    if (e >= N_EDGES) return;
    int d = dst[e];
    int p = atomicAdd(&g_deg[d], 1);
    g_colidx[g_rowptr[d] + p] = src[e];
}

// ---------------------------------------------------------------------------
// Weight convert + transpose: out[m][n][k] = split(W_m[k][n])
// ---------------------------------------------------------------------------
__global__ void k_convW(const float* __restrict__ W1b, const float* __restrict__ Wa,
                        const float* __restrict__ Wb) {
    __shared__ float tile[32][33];
    int m = blockIdx.z;
    const float* W = (m == 0) ? W1b
                   : ((m & 1) ? Wa + (size_t)((m - 1) >> 1) * D * D
                              : Wb + (size_t)((m - 2) >> 1) * D * D);
    int tx = threadIdx.x, ty = threadIdx.y;
    int n0 = blockIdx.x * 32, k0 = blockIdx.y * 32;
#pragma unroll
    for (int j = 0; j < 32; j += 8)
        tile[ty + j][tx] = W[(k0 + ty + j) * D + n0 + tx];
    __syncthreads();
#pragma unroll
    for (int j = 0; j < 32; j += 8) {
        float v = tile[tx][ty + j];
        int n = n0 + ty + j, k = k0 + tx;
        __nv_bfloat16 hi = __float2bfloat16(v);
        __nv_bfloat16 lo = __float2bfloat16(v - __bfloat162float(hi));
        size_t o = (size_t)m * D * D + (size_t)n * D + k;
        g_Whi[o] = hi;
        g_Wlo[o] = lo;
    }
}

// ---------------------------------------------------------------------------
// Layer-1 aggregation + small GEMM (IN_F=16), emits split bf16 + relu
// ---------------------------------------------------------------------------
__global__ void k_scatter16(const float* __restrict__ x,
                            const int* __restrict__ src, const int* __restrict__ dst) {
    int idx = blockIdx.x * blockDim.x + threadIdx.x;
    if (idx >= N_EDGES * 4) return;
    int e = idx >> 2;
    int g = (idx & 3) << 2;
    int s = src[e], d = dst[e];
    float4 v = *(const float4*)&x[s * IN_F + g];
    red_add_v4(&g_agg16[d * IN_F + g], v);
}

__global__ void k_gemm16(const float* __restrict__ W, const float* __restrict__ bias) {
    int idx = blockIdx.x * blockDim.x + threadIdx.x;
    if (idx >= N_NODES * (D / 4)) return;
    int n = idx >> 7;
    int c = (idx & 127) << 2;
    float4 acc = *(const float4*)&bias[c];
    const float* arow = &g_agg16[n * IN_F];
#pragma unroll
    for (int k = 0; k < IN_F; k++) {
        float a = arow[k];
        float4 w = *(const float4*)&W[k * D + c];
        acc.x += a * w.x; acc.y += a * w.y; acc.z += a * w.z; acc.w += a * w.w;
    }
    acc.x = fmaxf(acc.x, 0.f); acc.y = fmaxf(acc.y, 0.f);
    acc.z = fmaxf(acc.z, 0.f); acc.w = fmaxf(acc.w, 0.f);
    ull pl;
    ull ph = split_pack4(acc, pl);
    *(ull*)&g_tHi[n * D + c] = ph;
    *(ull*)&g_tLo[n * D + c] = pl;
}

// ---------------------------------------------------------------------------
// CSR gather + fused BN-apply + hi/lo split.
// ---------------------------------------------------------------------------
__global__ __launch_bounds__(256)
void k_gather_bn(const float* __restrict__ h,
                 const float* __restrict__ gamma, const float* __restrict__ beta,
                 __nv_bfloat16* __restrict__ Hi, __nv_bfloat16* __restrict__ Lo) {
    int gw = (blockIdx.x * 256 + threadIdx.x) >> 5;
    if (gw >= N_NODES * 4) return;
    int lane = threadIdx.x & 31;
    int n = gw >> 2;
    int c = ((gw & 3) << 7) + lane * 4;

    float4 acc = *(const float4*)&h[(size_t)n * D + c];
    int e0 = g_rowptr[n], e1 = g_rowptr[n + 1];
    int e = e0;
    for (; e + 2 <= e1; e += 2) {
        int s0 = g_colidx[e], s1 = g_colidx[e + 1];
        float4 v0 = *(const float4*)&h[(size_t)s0 * D + c];
        float4 v1 = *(const float4*)&h[(size_t)s1 * D + c];
        acc.x += v0.x + v1.x; acc.y += v0.y + v1.y;
        acc.z += v0.z + v1.z; acc.w += v0.w + v1.w;
    }
    if (e < e1) {
        int s0 = g_colidx[e];
        float4 v0 = *(const float4*)&h[(size_t)s0 * D + c];
        acc.x += v0.x; acc.y += v0.y; acc.z += v0.z; acc.w += v0.w;
    }
    float cnt = (float)(e1 - e0 + 1);
    const float invN = 1.0f / N_NODES;
    float4 bs = *(const float4*)&g_bnsum[c];
    float4 bq = *(const float4*)&g_bnsq[c];
    float4 gm = *(const float4*)&gamma[c];
    float4 bt = *(const float4*)&beta[c];
    float m0 = bs.x * invN, m1 = bs.y * invN, m2 = bs.z * invN, m3 = bs.w * invN;
    float s0 = gm.x * rsqrtf(bq.x * invN - m0 * m0 + BN_EPS);
    float s1 = gm.y * rsqrtf(bq.y * invN - m1 * m1 + BN_EPS);
    float s2 = gm.z * rsqrtf(bq.z * invN - m2 * m2 + BN_EPS);
    float s3 = gm.w * rsqrtf(bq.w * invN - m3 * m3 + BN_EPS);
    float4 o;
    o.x = s0 * acc.x + cnt * (bt.x - s0 * m0);
    o.y = s1 * acc.y + cnt * (bt.y - s1 * m1);
    o.z = s2 * acc.z + cnt * (bt.z - s2 * m2);
    o.w = s3 * acc.w + cnt * (bt.w - s3 * m3);
    ull pl;
    ull ph = split_pack4(o, pl);
    *(ull*)&Hi[(size_t)n * D + c] = ph;
    *(ull*)&Lo[(size_t)n * D + c] = pl;
}

// ---------------------------------------------------------------------------
// HMMA GEMM: BM=64, BN=128, BK=32, 128 threads (4 warps, 32x64 warp tile),
// SW64-swizzled smem, cp.async double-buffered, 4 CTAs/SM.
// 3-term split: Ahi*Bhi + Ahi*Blo + Alo*Bhi, fp32 accum.
// mode 0: out f32 + relu + fused BN stats; mode 1: out split bf16 + relu.
// ---------------------------------------------------------------------------
#define BM 64
#define BN 128
#define BK 32
#define A_ARR 4096                 // 64 rows * 64 B
#define B_ARR 8192                 // 128 rows * 64 B
#define STG_B (2 * A_ARR + 2 * B_ARR)   // 24576
#define GEMM_SMEM (2 * STG_B)           // 49152

__global__ __launch_bounds__(128, 4)
void k_gemm512_mma(const __nv_bfloat16* __restrict__ Ahi,
                   const __nv_bfloat16* __restrict__ Alo,
                   const __nv_bfloat16* __restrict__ Bthi,
                   const __nv_bfloat16* __restrict__ Btlo,
                   const float* __restrict__ bias,
                   float* __restrict__ Cf,
                   __nv_bfloat16* __restrict__ Chi,
                   __nv_bfloat16* __restrict__ Clo,
                   int M, int mode) {
    extern __shared__ char sm[];
    const uint32_t sbase = smem_u32(sm);

    const int tid = threadIdx.x;
    const int lane = tid & 31;
    const int warp = tid >> 5;
    const int wm = warp & 1;       // 2 warps over M (32 rows each)
    const int wn = warp >> 1;      // 2 warps over N (64 cols each)
    const int rowBase = blockIdx.x * BM;
    const int colBase = blockIdx.y * BN;

    // producer coords
    const int ra = tid >> 2, ca = tid & 3;            // A: 2 rounds (ra, ra+32)
    const int rb = tid >> 2, cb = tid & 3;            // B: 4 rounds (rb + 32*j)

    float acc[2][8][4];
#pragma unroll
    for (int mi = 0; mi < 2; mi++)
#pragma unroll
        for (int ni = 0; ni < 8; ni++)
#pragma unroll
            for (int j = 0; j < 4; j++) acc[mi][ni][j] = 0.f;

#define PREFETCH(kc_, s_)                                                           \
    {                                                                               \
        const int k0_ = (kc_) * BK;                                                 \
        const uint32_t sb_ = sbase + (s_) * STG_B;                                  \
        _Pragma("unroll")                                                           \
        for (int j_ = 0; j_ < 2; j_++) {                                            \
            int r_ = ra + j_ * 32;                                                  \
            int ok_ = (rowBase + r_ < M) ? 16 : 0;                                  \
            uint32_t so_ = swz((uint32_t)(r_ * 64 + ca * 16));                      \
            cpasync16(sb_ + so_, &Ahi[(size_t)(rowBase + r_) * D + k0_ + ca * 8], ok_); \
            cpasync16(sb_ + A_ARR + so_, &Alo[(size_t)(rowBase + r_) * D + k0_ + ca * 8], ok_); \
        }                                                                           \
        _Pragma("unroll")                                                           \
        for (int j_ = 0; j_ < 4; j_++) {                                            \
            int r_ = rb + j_ * 32;                                                  \
            uint32_t so_ = swz((uint32_t)(r_ * 64 + cb * 16));                      \
            cpasync16(sb_ + 2 * A_ARR + so_, &Bthi[(size_t)(colBase + r_) * D + k0_ + cb * 8], 16); \
            cpasync16(sb_ + 2 * A_ARR + B_ARR + so_, &Btlo[(size_t)(colBase + r_) * D + k0_ + cb * 8], 16); \
        }                                                                           \
        cp_commit();                                                                \
    }

    PREFETCH(0, 0);

    for (int kc = 0; kc < D / BK; kc++) {
        const int s = kc & 1;
        if (kc + 1 < D / BK) {
            PREFETCH(kc + 1, s ^ 1);
            cp_wait1();
        } else {
            cp_wait0();
        }
        __syncthreads();

        const uint32_t sb = sbase + s * STG_B;
        const uint32_t aHiB = sb, aLoB = sb + A_ARR;
        const uint32_t bHiB = sb + 2 * A_ARR, bLoB = bHiB + B_ARR;

#pragma unroll
        for (int ks = 0; ks < 2; ks++) {
            const int kk = ks * 16;
            uint32_t ahi[2][4], alo[2][4];
#pragma unroll
            for (int mi = 0; mi < 2; mi++) {
                int row = wm * 32 + mi * 16 + (lane & 15);
                uint32_t off = swz((uint32_t)(row * 64 + kk * 2 + (lane >> 4) * 16));
                ldsm4(ahi[mi], aHiB + off);
                ldsm4(alo[mi], aLoB + off);
            }
            int brow = wn * 64 + (lane & 7) + ((lane >> 4) << 3);
            int bcolb = kk * 2 + ((lane >> 3) & 1) * 16;
#pragma unroll
            for (int np = 0; np < 4; np++) {
                uint32_t bhi4[4], blo4[4];
                uint32_t off = swz((uint32_t)((brow + np * 16) * 64 + bcolb));
                ldsm4(bhi4, bHiB + off);
                ldsm4(blo4, bLoB + off);
#pragma unroll
                for (int mi = 0; mi < 2; mi++) {
                    mma16816(acc[mi][2 * np + 0], ahi[mi], bhi4 + 0);
                    mma16816(acc[mi][2 * np + 0], ahi[mi], blo4 + 0);
                    mma16816(acc[mi][2 * np + 0], alo[mi], bhi4 + 0);
                    mma16816(acc[mi][2 * np + 1], ahi[mi], bhi4 + 2);
                    mma16816(acc[mi][2 * np + 1], ahi[mi], blo4 + 2);
                    mma16816(acc[mi][2 * np + 1], alo[mi], bhi4 + 2);
                }
            }
        }
        __syncthreads();
    }
#undef PREFETCH

    // ---- epilogue
    if (mode == 0) {
        float* scol = (float*)sm;          // 128 floats
        float* qcol = scol + 128;          // 128 floats
        scol[tid] = 0.f; qcol[tid] = 0.f;
        __syncthreads();
#pragma unroll
        for (int ni = 0; ni < 8; ni++) {
            int col = colBase + wn * 64 + ni * 8 + (lane & 3) * 2;
            float b0 = bias[col], b1 = bias[col + 1];
            float s0 = 0.f, q0 = 0.f, s1 = 0.f, q1 = 0.f;
#pragma unroll
            for (int mi = 0; mi < 2; mi++) {
                int row0 = rowBase + wm * 32 + mi * 16 + (lane >> 2);
                int row1 = row0 + 8;
                float v00 = fmaxf(acc[mi][ni][0] + b0, 0.f);
                float v01 = fmaxf(acc[mi][ni][1] + b1, 0.f);
                float v10 = fmaxf(acc[mi][ni][2] + b0, 0.f);
                float v11 = fmaxf(acc[mi][ni][3] + b1, 0.f);
                if (row0 < M) {
                    *(float2*)&Cf[(size_t)row0 * D + col] = make_float2(v00, v01);
                    s0 += v00; q0 += v00 * v00; s1 += v01; q1 += v01 * v01;
                }
                if (row1 < M) {
                    *(float2*)&Cf[(size_t)row1 * D + col] = make_float2(v10, v11);
                    s0 += v10; q0 += v10 * v10; s1 += v11; q1 += v11 * v11;
                }
            }
#pragma unroll
            for (int o = 4; o < 32; o <<= 1) {
                s0 += __shfl_xor_sync(0xffffffffu, s0, o);
                q0 += __shfl_xor_sync(0xffffffffu, q0, o);
                s1 += __shfl_xor_sync(0xffffffffu, s1, o);
                q1 += __shfl_xor_sync(0xffffffffu, q1, o);
            }
            if (lane < 4) {
                int lc = wn * 64 + ni * 8 + lane * 2;
                atomicAdd(&scol[lc], s0);
                atomicAdd(&qcol[lc], q0);
                atomicAdd(&scol[lc + 1], s1);
                atomicAdd(&qcol[lc + 1], q1);
            }
        }
        __syncthreads();
        atomicAdd(&g_bnsum[colBase + tid], scol[tid]);
        atomicAdd(&g_bnsq[colBase + tid], qcol[tid]);
    } else {
#pragma unroll
        for (int mi = 0; mi < 2; mi++) {
            int row0 = rowBase + wm * 32 + mi * 16 + (lane >> 2);
            int row1 = row0 + 8;
#pragma unroll
            for (int ni = 0; ni < 8; ni++) {
                int col = colBase + wn * 64 + ni * 8 + (lane & 3) * 2;
                float b0 = bias[col], b1 = bias[col + 1];
                float v00 = fmaxf(acc[mi][ni][0] + b0, 0.f);
                float v01 = fmaxf(acc[mi][ni][1] + b1, 0.f);
                float v10 = fmaxf(acc[mi][ni][2] + b0, 0.f);
                float v11 = fmaxf(acc[mi][ni][3] + b1, 0.f);
                __nv_bfloat16 h0 = __float2bfloat16(v00), h1 = __float2bfloat16(v01);
                __nv_bfloat16 h2 = __float2bfloat16(v10), h3 = __float2bfloat16(v11);
                __nv_bfloat16 l0 = __float2bfloat16(v00 - __bfloat162float(h0));
                __nv_bfloat16 l1 = __float2bfloat16(v01 - __bfloat162float(h1));
                __nv_bfloat16 l2 = __float2bfloat16(v10 - __bfloat162float(h2));
                __nv_bfloat16 l3 = __float2bfloat16(v11 - __bfloat162float(h3));
                if (row0 < M) {
                    *(uint32_t*)&Chi[(size_t)row0 * D + col] =
                        (uint32_t)__bfloat16_as_ushort(h0) | ((uint32_t)__bfloat16_as_ushort(h1) << 16);
                    *(uint32_t*)&Clo[(size_t)row0 * D + col] =
                        (uint32_t)__bfloat16_as_ushort(l0) | ((uint32_t)__bfloat16_as_ushort(l1) << 16);
                }
                if (row1 < M) {
                    *(uint32_t*)&Chi[(size_t)row1 * D + col] =
                        (uint32_t)__bfloat16_as_ushort(h2) | ((uint32_t)__bfloat16_as_ushort(h3) << 16);
                    *(uint32_t*)&Clo[(size_t)row1 * D + col] =
                        (uint32_t)__bfloat16_as_ushort(l2) | ((uint32_t)__bfloat16_as_ushort(l3) << 16);
                }
            }
        }
    }
}

// ---------------------------------------------------------------------------
// Pool + head (BN affine applied to pooled means inside k_head)
// ---------------------------------------------------------------------------
__global__ void k_poolscatter(const float* __restrict__ h, const int* __restrict__ batch) {
    int idx = blockIdx.x * blockDim.x + threadIdx.x;
    if (idx >= N_NODES * (D / 4)) return;
    int n = idx >> 7;
    int g = (idx & 127) << 2;
    int b = batch[n];
    float4 v = *(const float4*)&h[n * D + g];
    red_add_v4(&g_pool[b * D + g], v);
}
__global__ void k_count(const int* __restrict__ batch) {
    int n = blockIdx.x * blockDim.x + threadIdx.x;
    if (n < N_NODES) atomicAdd(&g_cnt[batch[n]], 1.0f);
}
__global__ void k_head(const float* __restrict__ Wfc, const float* __restrict__ bfc,
                       const float* __restrict__ Wlog, const float* __restrict__ blog,
                       const float* __restrict__ gamma, const float* __restrict__ beta,
                       float* __restrict__ out) {
    __shared__ float sp[D];
    __shared__ float sf[D];
    int g = blockIdx.x;
    int t = threadIdx.x;
    float cnt = g_cnt[g];
    float invc = 1.0f / fmaxf(cnt, 1.0f);
    const float invN = 1.0f / N_NODES;
    float mean = g_bnsum[t] * invN;
    float var = g_bnsq[t] * invN - mean * mean;
    float sc = gamma[t] * rsqrtf(var + BN_EPS);
    sp[t] = sc * (g_pool[g * D + t] * invc) + (cnt * invc) * (beta[t] - sc * mean);
    __syncthreads();
    float f = bfc[t];
    for (int k = 0; k < D; k++) f += sp[k] * Wfc[k * D + t];
    sf[t] = tanhf(f);
    __syncthreads();
    if (t < N_OUT) {
        float l = blog[t];
        for (int k = 0; k < D; k++) l += sf[k] * Wlog[k * N_OUT + t];
        out[g * N_OUT + t] = l;
    }
}

// ---------------------------------------------------------------------------
// Launcher
// ---------------------------------------------------------------------------
extern "C" void kernel_launch(void* const* d_in, const int* in_sizes, int n_in,
                              void* d_out, int out_size) {
    const float* x     = (const float*)d_in[0];
    const int*   ei    = (const int*)d_in[1];
    const int*   batch = (const int*)d_in[2];
    const float* W1a   = (const float*)d_in[3];
    const float* b1a   = (const float*)d_in[4];
    const float* W1b   = (const float*)d_in[5];
    const float* b1b   = (const float*)d_in[6];
    const float* Wa    = (const float*)d_in[7];
    const float* ba    = (const float*)d_in[8];
    const float* Wb    = (const float*)d_in[9];
    const float* bb    = (const float*)d_in[10];
    const float* bn_g  = (const float*)d_in[11];
    const float* bn_b  = (const float*)d_in[12];
    const float* Wfc   = (const float*)d_in[13];
    const float* bfc   = (const float*)d_in[14];
    const float* Wlog  = (const float*)d_in[15];
    const float* blog  = (const float*)d_in[16];
    float* out = (float*)d_out;

    const int* src = ei;
    const int* dst = ei + N_EDGES;

    float *h, *agg16;
    __nv_bfloat16 *whi, *wlo, *thi, *tlo, *ahi, *alo;
    cudaGetSymbolAddress((void**)&h,     g_h);
    cudaGetSymbolAddress((void**)&agg16, g_agg16);
    cudaGetSymbolAddress((void**)&whi,   g_Whi);
    cudaGetSymbolAddress((void**)&wlo,   g_Wlo);
    cudaGetSymbolAddress((void**)&thi,   g_tHi);
    cudaGetSymbolAddress((void**)&tlo,   g_tLo);
    cudaGetSymbolAddress((void**)&ahi,   g_aHi);
    cudaGetSymbolAddress((void**)&alo,   g_aLo);

    cudaFuncSetAttribute(k_gemm512_mma, cudaFuncAttributeMaxDynamicSharedMemorySize, GEMM_SMEM);

    const int TB = 256;
    dim3 gemmGrid((N_NODES + BM - 1) / BM, D / BN);   // (157, 4)
    const size_t DD = (size_t)D * D;

    // CSR build + weight pre-convert
    k_zero_deg<<<(N_NODES + TB - 1) / TB, TB>>>();
    k_deg<<<(N_EDGES + TB - 1) / TB, TB>>>(dst);
    k_scan<<<1, 1024>>>();
    k_fill<<<(N_EDGES + TB - 1) / TB, TB>>>(src, dst);
    k_convW<<<dim3(16, 16, 9), dim3(32, 8)>>>(W1b, Wa, Wb);

    // ---- layer 1 ----
    k_copy4<<<(N_NODES * IN_F / 4 + TB - 1) / TB, TB>>>(agg16, x, N_NODES * IN_F / 4);
    k_scatter16<<<(N_EDGES * 4 + TB - 1) / TB, TB>>>(x, src, dst);
    k_gemm16<<<(N_NODES * 128 + TB - 1) / TB, TB>>>(W1a, b1a);
    k_zero_bn<<<2, 256>>>();
    k_gemm512_mma<<<gemmGrid, 128, GEMM_SMEM>>>(thi, tlo, whi, wlo, b1b, h,
                                                ((__nv_bfloat16*)0), ((__nv_bfloat16*)0),
                                                N_NODES, 0);

    // ---- layers 2..5 ----
    for (int i = 0; i < 4; i++) {
        k_gather_bn<<<(N_NODES * 4 * 32 + TB - 1) / TB, TB>>>(h, bn_g + i * D, bn_b + i * D,
                                                              ahi, alo);
        k_gemm512_mma<<<gemmGrid, 128, GEMM_SMEM>>>(ahi, alo,
                                                    whi + (size_t)(1 + 2 * i) * DD,
                                                    wlo + (size_t)(1 + 2 * i) * DD,
                                                    ba + i * D, ((float*)0), thi, tlo,
                                                    N_NODES, 1);
        k_zero_bn<<<2, 256>>>();
        k_gemm512_mma<<<gemmGrid, 128, GEMM_SMEM>>>(thi, tlo,
                                                    whi + (size_t)(2 + 2 * i) * DD,
                                                    wlo + (size_t)(2 + 2 * i) * DD,
                                                    bb + i * D, h,
                                                    ((__nv_bfloat16*)0), ((__nv_bfloat16*)0),
                                                    N_NODES, 0);
    }

    // ---- pooling + head (BN5 applied on pooled means) ----
    k_zero_pool<<<(N_GRAPHS * D + TB - 1) / TB, TB>>>();
    k_poolscatter<<<(N_NODES * 128 + TB - 1) / TB, TB>>>(h, batch);
    k_count<<<(N_NODES + TB - 1) / TB, TB>>>(batch);
    k_head<<<N_GRAPHS, D>>>(Wfc, bfc, Wlog, blog, bn_g + 4 * D, bn_b + 4 * D, out);
}